// round 9
// baseline (speedup 1.0000x reference)
#include <cuda_runtime.h>
#include <cuda_bf16.h>
#include <math.h>
#include <stdint.h>

// Problem constants (fixed by setup_inputs)
#define BATCH   512
#define TTEXT   64
#define EDIM    50
#define HDIM    32
#define NTL     32768
#define TTL     32
#define DNORM   49
#define FC_IN   305   // 64 + 49 + 64 + 64 + 64
#define GEMM_ROWS 64  // rows per GEMM CTA

typedef unsigned long long u64t;

// -------- device scratch (static; no runtime allocation) --------
__device__ float g_hn[BATCH * 64];            // text biRNN final hidden [B, 2H]
__device__ float g_h2[NTL * 64];              // timeline biRNN final hidden [N, 2H]
__device__ float g_mean[BATCH * 64];
__device__ float g_min[BATCH * 64];
__device__ float g_max[BATCH * 64];
__device__ float g_u2[(size_t)NTL * TTL * 64];   // u = x@Wih^T, timeline (268 MB)
__device__ float g_u1[BATCH * TTEXT * 64];       // u for text (8 MB)
__device__ __nv_bfloat16 g_wh[2][64][72];        // Wih bf16-hi  [model][n][k]
__device__ __nv_bfloat16 g_wl[2][64][72];        // Wih bf16-lo

// ---------------- packed f32x2 helpers ----------------
__device__ __forceinline__ u64t pk2(float a, float b) {
    u64t r; asm("mov.b64 %0,{%1,%2};" : "=l"(r) : "f"(a), "f"(b)); return r;
}
__device__ __forceinline__ void upk2(u64t v, float& a, float& b) {
    asm("mov.b64 {%0,%1},%2;" : "=f"(a), "=f"(b) : "l"(v));
}
__device__ __forceinline__ u64t fma2(u64t a, u64t b, u64t c) {
    u64t d; asm("fma.rn.f32x2 %0,%1,%2,%3;" : "=l"(d) : "l"(a), "l"(b), "l"(c)); return d;
}
__device__ __forceinline__ u64t add2(u64t a, u64t b) {
    u64t d; asm("add.rn.f32x2 %0,%1,%2;" : "=l"(d) : "l"(a), "l"(b)); return d;
}

// tanh(x) = 1 - 2/(e^{2x}+1) via MUFU ex2/rcp (rel err ~1e-6)
__device__ __forceinline__ float fast_tanh(float x) {
    float e, r;
    asm("ex2.approx.f32 %0,%1;" : "=f"(e) : "f"(x * 2.8853900817779268f));
    asm("rcp.approx.f32 %0,%1;" : "=f"(r) : "f"(e + 1.0f));
    return fmaf(-2.0f, r, 1.0f);
}
__device__ __forceinline__ float fast_sigmoid(float x) {
    float e, r;
    asm("ex2.approx.f32 %0,%1;" : "=f"(e) : "f"(-x * 1.4426950408889634f));
    asm("rcp.approx.f32 %0,%1;" : "=f"(r) : "f"(e + 1.0f));
    return r;
}

// ---------------- cp.async helpers (8-byte only; x rows are 200B = 8 mod 16,
// so 16-byte cp.async would trap on odd rows) ----------------
#define CP_ASYNC8(dst32, srcptr) \
    asm volatile("cp.async.ca.shared.global [%0], [%1], 8;" :: "r"(dst32), "l"(srcptr))
#define CP_COMMIT() asm volatile("cp.async.commit_group;" ::: "memory")
#define CP_WAIT0()  asm volatile("cp.async.wait_group 0;" ::: "memory")

// mma.sync m16n8k16 row.col f32.bf16.bf16.f32, D += A*B
#define MMA16816(C, A, B0, B1) \
    asm volatile("mma.sync.aligned.m16n8k16.row.col.f32.bf16.bf16.f32 " \
        "{%0,%1,%2,%3}, {%4,%5,%6,%7}, {%8,%9}, {%0,%1,%2,%3};" \
        : "+f"((C)[0]), "+f"((C)[1]), "+f"((C)[2]), "+f"((C)[3]) \
        : "r"((A)[0]), "r"((A)[1]), "r"((A)[2]), "r"((A)[3]), "r"(B0), "r"(B1))

// ============================================================================
// Setup: convert Wih (both models, both dirs) to bf16 hi/lo, layout [n=dir*32+
// unit][k padded to 72, zeros beyond 50]. One tiny launch.
// ============================================================================
__global__ void setup_w_kernel(const float* __restrict__ l_Wif, const float* __restrict__ l_Wib,
                               const float* __restrict__ t_Wif, const float* __restrict__ t_Wib)
{
    for (int idx = threadIdx.x; idx < 2 * 64 * 72; idx += blockDim.x) {
        int m = idx / (64 * 72);
        int rem = idx % (64 * 72);
        int n = rem / 72, k = rem % 72;
        int d = n >> 5, unit = n & 31;
        const float* W = (m == 0) ? (d ? l_Wib : l_Wif) : (d ? t_Wib : t_Wif);
        float v = (k < EDIM) ? W[unit * EDIM + k] : 0.f;
        __nv_bfloat16 h = __float2bfloat16_rn(v);
        float r = v - __bfloat162float(h);
        g_wh[m][n][k] = h;
        g_wl[m][n][k] = __float2bfloat16_rn(r);
    }
}

// ============================================================================
// Tensor-core GEMM: U[row, n] = sum_k X[row, k] * Wih[n][k], bf16 split
// (Ah*Bh + Ah*Bl + Al*Bh; error ~2^-16). 64 rows per CTA; warp = 16 rows.
// A frags from smem (x converted fp32->bf16 hi/lo); B frags from L1-hot gmem.
// blocks [0, tlCTAs) -> timeline, rest -> text.
// ============================================================================
__global__ void __launch_bounds__(128) gemm_u_kernel(
    const float* __restrict__ Xl, float* __restrict__ Ul,
    const float* __restrict__ Xt, float* __restrict__ Ut, int tlCTAs)
{
    __shared__ __align__(16) float         xa[GEMM_ROWS * 52];   // staged x fp32
    __shared__ __align__(16) __nv_bfloat16 xh[GEMM_ROWS * 72];   // x hi
    __shared__ __align__(16) __nv_bfloat16 xl[GEMM_ROWS * 72];   // x lo

    const int tid = threadIdx.x, w = tid >> 5, lane = tid & 31;
    const bool isTL = (int)blockIdx.x < tlCTAs;
    const int  blk  = isTL ? blockIdx.x : (blockIdx.x - tlCTAs);
    const float* X  = (isTL ? Xl : Xt) + (size_t)blk * GEMM_ROWS * EDIM;
    float*       U  = (isTL ? Ul : Ut) + (size_t)blk * GEMM_ROWS * 64;
    const int mdl   = isTL ? 0 : 1;

    // stage x rows (200B each) into pitch-208B smem; 8-byte chunks (alignment!)
    {
        uint32_t sb = (uint32_t)__cvta_generic_to_shared(xa);
        const char* src = (const char*)X;
        for (int c = tid; c < GEMM_ROWS * 25; c += 128) {
            int row = c / 25, slot = c % 25;
            CP_ASYNC8(sb + row * 208 + slot * 8, src + row * 200 + slot * 8);
        }
        CP_COMMIT(); CP_WAIT0();
    }
    __syncthreads();

    // convert: 2 threads per row (k-halves); zero-pad k in [50,72)
    {
        const int r = tid & 63;
        const int half = tid >> 6;
        const float* xr = xa + r * 52;
        __nv_bfloat162* hr = (__nv_bfloat162*)(xh + r * 72);
        __nv_bfloat162* lr = (__nv_bfloat162*)(xl + r * 72);
        const __nv_bfloat162 z2 = __floats2bfloat162_rn(0.f, 0.f);
        const int p0 = half ? 13 : 0, p1 = half ? 36 : 13;
        for (int p = p0; p < p1; ++p) {
            __nv_bfloat162 h2 = z2, l2 = z2;
            if (p < 25) {
                float2 v = *(const float2*)(xr + 2 * p);
                h2 = __floats2bfloat162_rn(v.x, v.y);
                float2 hb = __bfloat1622float2(h2);
                l2 = __floats2bfloat162_rn(v.x - hb.x, v.y - hb.y);
            }
            hr[p] = h2;
            lr[p] = l2;
        }
    }
    __syncthreads();

    // mma: warp covers rows [w*16, w*16+16), all 64 output cols
    const int g = lane >> 2, t = lane & 3;
    const int m0 = w * 16;

    uint32_t Ah[4][4], Al[4][4];             // [ktile][frag reg]
#pragma unroll
    for (int kt = 0; kt < 4; ++kt) {
        const int ko = kt * 16 + t * 2;
        const int r0 = m0 + g, r1 = m0 + g + 8;
        Ah[kt][0] = *(const uint32_t*)(xh + r0 * 72 + ko);
        Ah[kt][1] = *(const uint32_t*)(xh + r1 * 72 + ko);
        Ah[kt][2] = *(const uint32_t*)(xh + r0 * 72 + ko + 8);
        Ah[kt][3] = *(const uint32_t*)(xh + r1 * 72 + ko + 8);
        Al[kt][0] = *(const uint32_t*)(xl + r0 * 72 + ko);
        Al[kt][1] = *(const uint32_t*)(xl + r1 * 72 + ko);
        Al[kt][2] = *(const uint32_t*)(xl + r0 * 72 + ko + 8);
        Al[kt][3] = *(const uint32_t*)(xl + r1 * 72 + ko + 8);
    }

    const __nv_bfloat16* WH = &g_wh[mdl][0][0];
    const __nv_bfloat16* WL = &g_wl[mdl][0][0];

#pragma unroll
    for (int nc = 0; nc < 4; ++nc) {         // 16 output cols per chunk
        float c[2][4];
#pragma unroll
        for (int nt = 0; nt < 2; ++nt) { c[nt][0] = c[nt][1] = c[nt][2] = c[nt][3] = 0.f; }
#pragma unroll
        for (int kt = 0; kt < 4; ++kt) {
            const int ko = kt * 16 + t * 2;
#pragma unroll
            for (int nt = 0; nt < 2; ++nt) {
                const int n = nc * 16 + nt * 8 + g;
                uint32_t bh0 = *(const uint32_t*)(WH + n * 72 + ko);
                uint32_t bh1 = *(const uint32_t*)(WH + n * 72 + ko + 8);
                uint32_t bl0 = *(const uint32_t*)(WL + n * 72 + ko);
                uint32_t bl1 = *(const uint32_t*)(WL + n * 72 + ko + 8);
                MMA16816(c[nt], Ah[kt], bh0, bh1);
                MMA16816(c[nt], Ah[kt], bl0, bl1);
                MMA16816(c[nt], Al[kt], bh0, bh1);
            }
        }
#pragma unroll
        for (int nt = 0; nt < 2; ++nt) {
            const int col = nc * 16 + nt * 8 + t * 2;
            const int row = m0 + g;
            *(float2*)(U + row * 64 + col)       = make_float2(c[nt][0], c[nt][1]);
            *(float2*)(U + (row + 8) * 64 + col) = make_float2(c[nt][2], c[nt][3]);
        }
    }
}

// ============================================================================
// Recurrence: h_t = tanh(u_t + bias + h_{t-1}·Whh^T), final h only.
// One warp = (8 sequences, 1 direction); lane = hidden unit. Whh in registers
// (natural pairs), u via coalesced LDG.32 with distance-2 register prefetch,
// h double-buffered in smem (LDS.128 broadcast).
// blocks [0, tlBlocks) -> timeline, rest -> text.
// ============================================================================
__global__ void __launch_bounds__(128, 4) rec_kernel(
    int tlBlocks,
    const float* __restrict__ U2, float* __restrict__ H2o, int Tl,
    const float* __restrict__ l_Whf, const float* __restrict__ l_Whb,
    const float* __restrict__ l_bif, const float* __restrict__ l_bhf,
    const float* __restrict__ l_bib, const float* __restrict__ l_bhb,
    const float* __restrict__ U1, float* __restrict__ H1o, int Tt,
    const float* __restrict__ t_Whf, const float* __restrict__ t_Whb,
    const float* __restrict__ t_bif, const float* __restrict__ t_bhf,
    const float* __restrict__ t_bib, const float* __restrict__ t_bhb)
{
    __shared__ __align__(16) float sHf[4][2][8][HDIM];   // 8 KB

    const int tid = threadIdx.x, w = tid >> 5, lane = tid & 31;
    const bool isTL = (int)blockIdx.x < tlBlocks;
    const int  blk  = isTL ? blockIdx.x : (blockIdx.x - tlBlocks);
    const float* U  = isTL ? U2 : U1;
    float*    Hout  = isTL ? H2o : H1o;
    const int T     = isTL ? Tl : Tt;

    const int gw = blk * 4 + w;
    const int gI = gw >> 1;          // group of 8 sequences
    const int d  = gw & 1;           // direction

    const float* Wh = isTL ? (d ? l_Whb : l_Whf) : (d ? t_Whb : t_Whf);
    const float* bi = isTL ? (d ? l_bib : l_bif) : (d ? t_bib : t_bif);
    const float* bh = isTL ? (d ? l_bhb : l_bhf) : (d ? t_bhb : t_bhf);

    u64t wh[16];   // natural pairs {Wh[l][2i], Wh[l][2i+1]}
    {
        const u64t* Wh2 = (const u64t*)(Wh + lane * HDIM);
#pragma unroll
        for (int i = 0; i < 16; ++i) wh[i] = Wh2[i];
    }
    const float bias = bi[lane] + bh[lane];

    const int s0  = 8 * gI;
    const int sgn = d ? -64 : 64;
    const float* base = U + ((size_t)s0 * T + (d ? T - 1 : 0)) * 64 + d * 32 + lane;
    int sOff[8];
#pragma unroll
    for (int s = 0; s < 8; ++s) sOff[s] = s * T * 64;

    float uc[8], un[8];
#pragma unroll
    for (int s = 0; s < 8; ++s) uc[s] = base[sOff[s]];
#pragma unroll
    for (int s = 0; s < 8; ++s) un[s] = (T > 1) ? base[sOff[s] + sgn] : 0.f;
    const float* pf = base + 2 * sgn;

#pragma unroll
    for (int s = 0; s < 8; ++s) sHf[w][0][s][lane] = 0.f;
    __syncwarp();

    float hl[8];
#pragma unroll
    for (int s = 0; s < 8; ++s) hl[s] = 0.f;

    for (int t = 0; t < T; ++t) {
        const int cur = t & 1, nxt = cur ^ 1;

        // prefetch u_{t+2} (2-iteration latency slack)
        float ur[8];
        if (t + 2 < T) {
#pragma unroll
            for (int s = 0; s < 8; ++s) ur[s] = pf[sOff[s]];
        } else {
#pragma unroll
            for (int s = 0; s < 8; ++s) ur[s] = 0.f;
        }
        pf += sgn;

        // recurrence for step t
#pragma unroll
        for (int s = 0; s < 8; ++s) {
            const ulonglong2* h4 = (const ulonglong2*)&sHf[w][cur][s][0];
            u64t c0 = 0ull, c1 = 0ull;
#pragma unroll
            for (int i = 0; i < 8; ++i) {
                ulonglong2 hh = h4[i];             // LDS.128 broadcast
                c0 = fma2(hh.x, wh[2 * i],     c0);
                c1 = fma2(hh.y, wh[2 * i + 1], c1);
            }
            c0 = add2(c0, c1);
            float f0, f1; upk2(c0, f0, f1);
            hl[s] = fast_tanh(uc[s] + bias + f0 + f1);
        }
#pragma unroll
        for (int s = 0; s < 8; ++s) sHf[w][nxt][s][lane] = hl[s];
        __syncwarp();
#pragma unroll
        for (int s = 0; s < 8; ++s) { uc[s] = un[s]; un[s] = ur[s]; }
    }

    const int off = d * 32 + lane;
#pragma unroll
    for (int s = 0; s < 8; ++s)
        Hout[(size_t)(s0 + s) * 64 + off] = hl[s];
}

// ============================================================================
// Ragged segment mean/min/max over g_h2. One block (64 threads) per batch row.
// ============================================================================
__global__ void seg_kernel(const int* __restrict__ elems)
{
    const int b   = blockIdx.x;
    const int tid = threadIdx.x;   // 0..63
    __shared__ int sred[64];

    int partial = 0;
    for (int i = tid; i < b; i += 64) partial += elems[i];
    sred[tid] = partial;
    __syncthreads();
    for (int s = 32; s; s >>= 1) {
        if (tid < s) sred[tid] += sred[tid + s];
        __syncthreads();
    }
    const int off = sred[0];
    const int cnt = elems[b];

    float s = 0.f, mn = 3.402823466e38f, mx = -3.402823466e38f;
    const float* base = g_h2 + (size_t)off * 64 + tid;
    int r = 0;
    for (; r + 4 <= cnt; r += 4) {
        float v0 = base[(size_t)(r + 0) * 64];
        float v1 = base[(size_t)(r + 1) * 64];
        float v2 = base[(size_t)(r + 2) * 64];
        float v3 = base[(size_t)(r + 3) * 64];
        s += (v0 + v1) + (v2 + v3);
        mn = fminf(mn, fminf(fminf(v0, v1), fminf(v2, v3)));
        mx = fmaxf(mx, fmaxf(fmaxf(v0, v1), fmaxf(v2, v3)));
    }
    for (; r < cnt; ++r) {
        float v = base[(size_t)r * 64];
        s += v; mn = fminf(mn, v); mx = fmaxf(mx, v);
    }
    g_mean[b * 64 + tid] = s / (float)cnt;
    g_min[b * 64 + tid]  = mn;
    g_max[b * 64 + tid]  = mx;
}

// ============================================================================
// Head: concat(305) -> fc1 tanh -> fc2 sigmoid. 128 threads per batch row.
// ============================================================================
__global__ void __launch_bounds__(128) head_kernel(
    const float* __restrict__ normal,
    const float* __restrict__ fc1w, const float* __restrict__ fc1b,
    const float* __restrict__ fc2w, const float* __restrict__ fc2b,
    float* __restrict__ out)
{
    const int b    = blockIdx.x;
    const int tid  = threadIdx.x;
    const int wq   = tid >> 5;
    const int lane = tid & 31;
    __shared__ float xr[FC_IN + 3];
    __shared__ float part[4][32];

    if (tid < 64) {
        xr[tid]       = g_hn[b * 64 + tid];
        xr[113 + tid] = g_mean[b * 64 + tid];
        xr[177 + tid] = g_min[b * 64 + tid];
        xr[241 + tid] = g_max[b * 64 + tid];
    }
    for (int i = tid; i < DNORM; i += 128) xr[64 + i] = normal[b * DNORM + i];
    __syncthreads();

    const int k0 = wq * 76;
    const int k1 = (wq == 3) ? FC_IN : k0 + 76;
    const float* wrow = fc1w + lane * FC_IN;
    float a0 = 0.f, a1 = 0.f, a2 = 0.f, a3 = 0.f;
    int k = k0;
    for (; k + 4 <= k1; k += 4) {
        a0 += xr[k]     * wrow[k];
        a1 += xr[k + 1] * wrow[k + 1];
        a2 += xr[k + 2] * wrow[k + 2];
        a3 += xr[k + 3] * wrow[k + 3];
    }
    for (; k < k1; ++k) a0 += xr[k] * wrow[k];
    part[wq][lane] = (a0 + a1) + (a2 + a3);
    __syncthreads();

    if (wq == 0) {
        float acc = fc1b[lane] + part[0][lane] + part[1][lane] + part[2][lane] + part[3][lane];
        float pv = fast_tanh(acc) * fc2w[lane];
#pragma unroll
        for (int o = 16; o; o >>= 1) pv += __shfl_xor_sync(0xffffffffu, pv, o);
        if (lane == 0) out[b] = fast_sigmoid(pv + fc2b[0]);
    }
}

// ============================================================================
// kernel_launch
// ============================================================================
extern "C" void kernel_launch(void* const* d_in, const int* in_sizes, int n_in,
                              void* d_out, int out_size)
{
    const float* normal   = (const float*)d_in[0];
    const float* text     = (const float*)d_in[1];
    const float* timeline = (const float*)d_in[2];

    const int* elems;
    int base;
    if (in_sizes[3] == BATCH) { elems = (const int*)d_in[3]; base = 4; }
    else                      { elems = (const int*)d_in[n_in - 1]; base = 3; }

    const float* r1[8];
    const float* r2[8];
    for (int i = 0; i < 8; ++i) r1[i] = (const float*)d_in[base + i];
    for (int i = 0; i < 8; ++i) r2[i] = (const float*)d_in[base + 8 + i];
    const float* fc1w = (const float*)d_in[base + 16];
    const float* fc1b = (const float*)d_in[base + 17];
    const float* fc2w = (const float*)d_in[base + 18];
    const float* fc2b = (const float*)d_in[base + 19];
    // per dir: wi, wh, bi, bh ; fwd then bwd

    float* hn; cudaGetSymbolAddress((void**)&hn, g_hn);
    float* h2; cudaGetSymbolAddress((void**)&h2, g_h2);
    float* u1; cudaGetSymbolAddress((void**)&u1, g_u1);
    float* u2; cudaGetSymbolAddress((void**)&u2, g_u2);

    // 1. convert Wih to bf16 hi/lo (model 0 = timeline, 1 = text)
    setup_w_kernel<<<1, 256>>>(r2[0], r2[4], r1[0], r1[4]);

    // 2. tensor-core input GEMM: timeline 16384 CTAs + text 512 CTAs
    const int tlG = (NTL * TTL) / GEMM_ROWS;      // 16384
    const int txG = (BATCH * TTEXT) / GEMM_ROWS;  // 512
    gemm_u_kernel<<<tlG + txG, 128>>>(timeline, u2, text, u1, tlG);

    // 3. recurrence: warp = (8 seqs, 1 dir), 4 warps/block
    const int tlB = (NTL / 8 * 2) / 4;     // 2048 blocks
    const int txB = (BATCH / 8 * 2) / 4;   // 32 blocks
    rec_kernel<<<tlB + txB, 128>>>(
        tlB,
        u2, h2, TTL, r2[1], r2[5], r2[2], r2[3], r2[6], r2[7],
        u1, hn, TTEXT, r1[1], r1[5], r1[2], r1[3], r1[6], r1[7]);

    seg_kernel<<<BATCH, 64>>>(elems);

    head_kernel<<<BATCH, 128>>>(normal, fc1w, fc1b, fc2w, fc2b, (float*)d_out);
}

// round 11
// speedup vs baseline: 1.0852x; 1.0852x over previous
#include <cuda_runtime.h>
#include <cuda_bf16.h>
#include <math.h>
#include <stdint.h>

// Problem constants (fixed by setup_inputs)
#define BATCH   512
#define TTEXT   64
#define EDIM    50
#define HDIM    32
#define NTL     32768
#define TTL     32
#define DNORM   49
#define FC_IN   305   // 64 + 49 + 64 + 64 + 64
#define GEMM_ROWS 64  // rows per GEMM CTA

typedef unsigned long long u64t;

// -------- device scratch (static; no runtime allocation) --------
__device__ float g_hn[BATCH * 64];            // text biRNN final hidden [B, 2H]
__device__ float g_h2[NTL * 64];              // timeline biRNN final hidden [N, 2H]
__device__ float g_mean[BATCH * 64];
__device__ float g_min[BATCH * 64];
__device__ float g_max[BATCH * 64];
__device__ float g_u2[(size_t)NTL * TTL * 64];   // u = x@Wih^T, timeline (268 MB)
__device__ float g_u1[BATCH * TTEXT * 64];       // u for text (8 MB)
__device__ __nv_bfloat16 g_wh[2][64][72];        // Wih bf16-hi  [model][n][k]
__device__ __nv_bfloat16 g_wl[2][64][72];        // Wih bf16-lo

// ---------------- packed f32x2 helpers ----------------
__device__ __forceinline__ u64t pk2(float a, float b) {
    u64t r; asm("mov.b64 %0,{%1,%2};" : "=l"(r) : "f"(a), "f"(b)); return r;
}
__device__ __forceinline__ void upk2(u64t v, float& a, float& b) {
    asm("mov.b64 {%0,%1},%2;" : "=f"(a), "=f"(b) : "l"(v));
}
__device__ __forceinline__ u64t fma2(u64t a, u64t b, u64t c) {
    u64t d; asm("fma.rn.f32x2 %0,%1,%2,%3;" : "=l"(d) : "l"(a), "l"(b), "l"(c)); return d;
}
__device__ __forceinline__ u64t add2(u64t a, u64t b) {
    u64t d; asm("add.rn.f32x2 %0,%1,%2;" : "=l"(d) : "l"(a), "l"(b)); return d;
}

// tanh(x) = 1 - 2/(e^{2x}+1) via MUFU ex2/rcp (rel err ~1e-6)
__device__ __forceinline__ float fast_tanh(float x) {
    float e, r;
    asm("ex2.approx.f32 %0,%1;" : "=f"(e) : "f"(x * 2.8853900817779268f));
    asm("rcp.approx.f32 %0,%1;" : "=f"(r) : "f"(e + 1.0f));
    return fmaf(-2.0f, r, 1.0f);
}
__device__ __forceinline__ float fast_sigmoid(float x) {
    float e, r;
    asm("ex2.approx.f32 %0,%1;" : "=f"(e) : "f"(-x * 1.4426950408889634f));
    asm("rcp.approx.f32 %0,%1;" : "=f"(r) : "f"(e + 1.0f));
    return r;
}

// ---------------- TMA 1D bulk + mbarrier helpers ----------------
__device__ __forceinline__ uint32_t smem_u32(const void* p) {
    return (uint32_t)__cvta_generic_to_shared(p);
}
__device__ __forceinline__ void mbar_init(uint32_t mb, uint32_t cnt) {
    asm volatile("mbarrier.init.shared.b64 [%0], %1;" :: "r"(mb), "r"(cnt) : "memory");
}
__device__ __forceinline__ void mbar_expect_tx(uint32_t mb, uint32_t bytes) {
    asm volatile("mbarrier.arrive.expect_tx.shared.b64 _, [%0], %1;"
                 :: "r"(mb), "r"(bytes) : "memory");
}
__device__ __forceinline__ void mbar_wait0(uint32_t mb) {
    asm volatile(
        "{\n\t.reg .pred P;\n\t"
        "W%=:\n\t"
        "mbarrier.try_wait.parity.acquire.cta.shared::cta.b64 P, [%0], 0, 0x989680;\n\t"
        "@!P bra W%=;\n\t}"
        :: "r"(mb) : "memory");
}
__device__ __forceinline__ void tma_bulk_g2s(uint32_t dst, const void* src,
                                             uint32_t bytes, uint32_t mb) {
    asm volatile(
        "cp.async.bulk.shared::cta.global.mbarrier::complete_tx::bytes [%0], [%1], %2, [%3];"
        :: "r"(dst), "l"(src), "r"(bytes), "r"(mb) : "memory");
}
__device__ __forceinline__ void tma_bulk_s2g(void* dst, uint32_t src, uint32_t bytes) {
    asm volatile("cp.async.bulk.global.shared::cta.bulk_group [%0], [%1], %2;"
                 :: "l"(dst), "r"(src), "r"(bytes) : "memory");
    asm volatile("cp.async.bulk.commit_group;" ::: "memory");
    asm volatile("cp.async.bulk.wait_group 0;" ::: "memory");
}

// mma.sync m16n8k16 row.col f32.bf16.bf16.f32, D += A*B
#define MMA16816(C, A, B0, B1) \
    asm volatile("mma.sync.aligned.m16n8k16.row.col.f32.bf16.bf16.f32 " \
        "{%0,%1,%2,%3}, {%4,%5,%6,%7}, {%8,%9}, {%0,%1,%2,%3};" \
        : "+f"((C)[0]), "+f"((C)[1]), "+f"((C)[2]), "+f"((C)[3]) \
        : "r"((A)[0]), "r"((A)[1]), "r"((A)[2]), "r"((A)[3]), "r"(B0), "r"(B1))

// ============================================================================
// Setup: convert Wih (both models, both dirs) to bf16 hi/lo, layout
// [n=dir*32+unit][k padded to 72, zeros beyond 50]. One tiny launch.
// ============================================================================
__global__ void setup_w_kernel(const float* __restrict__ l_Wif, const float* __restrict__ l_Wib,
                               const float* __restrict__ t_Wif, const float* __restrict__ t_Wib)
{
    for (int idx = threadIdx.x; idx < 2 * 64 * 72; idx += blockDim.x) {
        int m = idx / (64 * 72);
        int rem = idx % (64 * 72);
        int n = rem / 72, k = rem % 72;
        int d = n >> 5, unit = n & 31;
        const float* W = (m == 0) ? (d ? l_Wib : l_Wif) : (d ? t_Wib : t_Wif);
        float v = (k < EDIM) ? W[unit * EDIM + k] : 0.f;
        __nv_bfloat16 h = __float2bfloat16_rn(v);
        float r = v - __bfloat162float(h);
        g_wh[m][n][k] = h;
        g_wl[m][n][k] = __float2bfloat16_rn(r);
    }
}

// ============================================================================
// Tensor-core GEMM: U[row, n] = sum_k X[row, k] * Wih[n][k], bf16 split
// (Ah*Bh + Ah*Bl + Al*Bh). 64 rows per CTA; warp = 16 rows.
// x tile arrives via ONE TMA 1D bulk load (12800B contiguous); U tile leaves
// via ONE TMA 1D bulk store (16384B) after smem staging — near-zero copy
// issue cost (the R9 version burned ~200us on 8B cp.async + STG.64 issue).
// smem reuse: uo aliases xa/xh after A-frags are register-resident.
// blocks [0, tlCTAs) -> timeline, rest -> text.
// ============================================================================
__global__ void __launch_bounds__(128) gemm_u_kernel(
    const float* __restrict__ Xl, float* __restrict__ Ul,
    const float* __restrict__ Xt, float* __restrict__ Ut, int tlCTAs)
{
    // layout: xa [0,12800) fp32 flat; xh [12800,22016); xl [22016,31232)
    // uo aliases [0,16384) (written only after frag loads + sync)
    __shared__ __align__(16) char smem[31232];
    __shared__ __align__(8) u64t mbar;

    float*         xa = (float*)smem;
    __nv_bfloat16* xh = (__nv_bfloat16*)(smem + 12800);
    __nv_bfloat16* xl = (__nv_bfloat16*)(smem + 22016);
    float*         uo = (float*)smem;

    const int tid = threadIdx.x, w = tid >> 5, lane = tid & 31;
    const bool isTL = (int)blockIdx.x < tlCTAs;
    const int  blk  = isTL ? blockIdx.x : (blockIdx.x - tlCTAs);
    const float* X  = (isTL ? Xl : Xt) + (size_t)blk * GEMM_ROWS * EDIM;
    float*       U  = (isTL ? Ul : Ut) + (size_t)blk * GEMM_ROWS * 64;
    const int mdl   = isTL ? 0 : 1;

    // ---- one bulk TMA load: 64 rows x 200B = 12800B contiguous ----
    const uint32_t mb = smem_u32(&mbar);
    if (tid == 0) mbar_init(mb, 1);
    __syncthreads();
    if (tid == 0) {
        mbar_expect_tx(mb, GEMM_ROWS * EDIM * 4);
        tma_bulk_g2s(smem_u32(xa), X, GEMM_ROWS * EDIM * 4, mb);
    }
    mbar_wait0(mb);

    // convert: 2 threads per row (k-halves); zero-pad k in [50,72)
    {
        const int r = tid & 63;
        const int half = tid >> 6;
        const float* xr = xa + r * EDIM;
        __nv_bfloat162* hr = (__nv_bfloat162*)(xh + r * 72);
        __nv_bfloat162* lr = (__nv_bfloat162*)(xl + r * 72);
        const __nv_bfloat162 z2 = __floats2bfloat162_rn(0.f, 0.f);
        const int p0 = half ? 13 : 0, p1 = half ? 36 : 13;
        for (int p = p0; p < p1; ++p) {
            __nv_bfloat162 h2 = z2, l2 = z2;
            if (p < 25) {
                float2 v = *(const float2*)(xr + 2 * p);
                h2 = __floats2bfloat162_rn(v.x, v.y);
                float2 hb = __bfloat1622float2(h2);
                l2 = __floats2bfloat162_rn(v.x - hb.x, v.y - hb.y);
            }
            hr[p] = h2;
            lr[p] = l2;
        }
    }
    __syncthreads();

    // A-fragments -> registers (then xa/xh/xl are dead)
    const int g = lane >> 2, t = lane & 3;
    const int m0 = w * 16;

    uint32_t Ah[4][4], Al[4][4];             // [ktile][frag reg]
#pragma unroll
    for (int kt = 0; kt < 4; ++kt) {
        const int ko = kt * 16 + t * 2;
        const int r0 = m0 + g, r1 = m0 + g + 8;
        Ah[kt][0] = *(const uint32_t*)(xh + r0 * 72 + ko);
        Ah[kt][1] = *(const uint32_t*)(xh + r1 * 72 + ko);
        Ah[kt][2] = *(const uint32_t*)(xh + r0 * 72 + ko + 8);
        Ah[kt][3] = *(const uint32_t*)(xh + r1 * 72 + ko + 8);
        Al[kt][0] = *(const uint32_t*)(xl + r0 * 72 + ko);
        Al[kt][1] = *(const uint32_t*)(xl + r1 * 72 + ko);
        Al[kt][2] = *(const uint32_t*)(xl + r0 * 72 + ko + 8);
        Al[kt][3] = *(const uint32_t*)(xl + r1 * 72 + ko + 8);
    }
    __syncthreads();   // everyone's frags loaded -> safe to overwrite smem (uo)

    const __nv_bfloat16* WH = &g_wh[mdl][0][0];
    const __nv_bfloat16* WL = &g_wl[mdl][0][0];

#pragma unroll
    for (int nc = 0; nc < 4; ++nc) {         // 16 output cols per chunk
        float c[2][4];
#pragma unroll
        for (int nt = 0; nt < 2; ++nt) { c[nt][0] = c[nt][1] = c[nt][2] = c[nt][3] = 0.f; }
#pragma unroll
        for (int kt = 0; kt < 4; ++kt) {
            const int ko = kt * 16 + t * 2;
#pragma unroll
            for (int nt = 0; nt < 2; ++nt) {
                const int n = nc * 16 + nt * 8 + g;
                uint32_t bh0 = *(const uint32_t*)(WH + n * 72 + ko);
                uint32_t bh1 = *(const uint32_t*)(WH + n * 72 + ko + 8);
                uint32_t bl0 = *(const uint32_t*)(WL + n * 72 + ko);
                uint32_t bl1 = *(const uint32_t*)(WL + n * 72 + ko + 8);
                MMA16816(c[nt], Ah[kt], bh0, bh1);
                MMA16816(c[nt], Ah[kt], bl0, bl1);
                MMA16816(c[nt], Al[kt], bh0, bh1);
            }
        }
        // stage results to smem (STS.64, conflict-light)
#pragma unroll
        for (int nt = 0; nt < 2; ++nt) {
            const int col = nc * 16 + nt * 8 + t * 2;
            const int row = m0 + g;
            *(float2*)(uo + row * 64 + col)       = make_float2(c[nt][0], c[nt][1]);
            *(float2*)(uo + (row + 8) * 64 + col) = make_float2(c[nt][2], c[nt][3]);
        }
    }
    __syncthreads();

    // ---- one bulk TMA store: 64 rows x 64 f32 = 16384B contiguous ----
    if (tid == 0) {
        asm volatile("fence.proxy.async;" ::: "memory");
        tma_bulk_s2g(U, smem_u32(uo), GEMM_ROWS * 64 * 4);
    }
}

// ============================================================================
// Recurrence: h_t = tanh(u_t + bias + h_{t-1}·Whh^T), final h only.
// One warp = (8 sequences, 1 direction); lane = hidden unit. Whh in registers
// (natural pairs), u via coalesced LDG.32 with distance-2 register prefetch,
// h double-buffered in smem (LDS.128 broadcast).
// blocks [0, tlBlocks) -> timeline, rest -> text.
// ============================================================================
__global__ void __launch_bounds__(128, 4) rec_kernel(
    int tlBlocks,
    const float* __restrict__ U2, float* __restrict__ H2o, int Tl,
    const float* __restrict__ l_Whf, const float* __restrict__ l_Whb,
    const float* __restrict__ l_bif, const float* __restrict__ l_bhf,
    const float* __restrict__ l_bib, const float* __restrict__ l_bhb,
    const float* __restrict__ U1, float* __restrict__ H1o, int Tt,
    const float* __restrict__ t_Whf, const float* __restrict__ t_Whb,
    const float* __restrict__ t_bif, const float* __restrict__ t_bhf,
    const float* __restrict__ t_bib, const float* __restrict__ t_bhb)
{
    __shared__ __align__(16) float sHf[4][2][8][HDIM];   // 8 KB

    const int tid = threadIdx.x, w = tid >> 5, lane = tid & 31;
    const bool isTL = (int)blockIdx.x < tlBlocks;
    const int  blk  = isTL ? blockIdx.x : (blockIdx.x - tlBlocks);
    const float* U  = isTL ? U2 : U1;
    float*    Hout  = isTL ? H2o : H1o;
    const int T     = isTL ? Tl : Tt;

    const int gw = blk * 4 + w;
    const int gI = gw >> 1;          // group of 8 sequences
    const int d  = gw & 1;           // direction

    const float* Wh = isTL ? (d ? l_Whb : l_Whf) : (d ? t_Whb : t_Whf);
    const float* bi = isTL ? (d ? l_bib : l_bif) : (d ? t_bib : t_bif);
    const float* bh = isTL ? (d ? l_bhb : l_bhf) : (d ? t_bhb : t_bhf);

    u64t wh[16];   // natural pairs {Wh[l][2i], Wh[l][2i+1]}
    {
        const u64t* Wh2 = (const u64t*)(Wh + lane * HDIM);
#pragma unroll
        for (int i = 0; i < 16; ++i) wh[i] = Wh2[i];
    }
    const float bias = bi[lane] + bh[lane];

    const int s0  = 8 * gI;
    const int sgn = d ? -64 : 64;
    const float* base = U + ((size_t)s0 * T + (d ? T - 1 : 0)) * 64 + d * 32 + lane;
    int sOff[8];
#pragma unroll
    for (int s = 0; s < 8; ++s) sOff[s] = s * T * 64;

    float uc[8], un[8];
#pragma unroll
    for (int s = 0; s < 8; ++s) uc[s] = base[sOff[s]];
#pragma unroll
    for (int s = 0; s < 8; ++s) un[s] = (T > 1) ? base[sOff[s] + sgn] : 0.f;
    const float* pf = base + 2 * sgn;

#pragma unroll
    for (int s = 0; s < 8; ++s) sHf[w][0][s][lane] = 0.f;
    __syncwarp();

    float hl[8];
#pragma unroll
    for (int s = 0; s < 8; ++s) hl[s] = 0.f;

    for (int t = 0; t < T; ++t) {
        const int cur = t & 1, nxt = cur ^ 1;

        // prefetch u_{t+2} (2-iteration latency slack)
        float ur[8];
        if (t + 2 < T) {
#pragma unroll
            for (int s = 0; s < 8; ++s) ur[s] = pf[sOff[s]];
        } else {
#pragma unroll
            for (int s = 0; s < 8; ++s) ur[s] = 0.f;
        }
        pf += sgn;

        // recurrence for step t
#pragma unroll
        for (int s = 0; s < 8; ++s) {
            const ulonglong2* h4 = (const ulonglong2*)&sHf[w][cur][s][0];
            u64t c0 = 0ull, c1 = 0ull;
#pragma unroll
            for (int i = 0; i < 8; ++i) {
                ulonglong2 hh = h4[i];             // LDS.128 broadcast
                c0 = fma2(hh.x, wh[2 * i],     c0);
                c1 = fma2(hh.y, wh[2 * i + 1], c1);
            }
            c0 = add2(c0, c1);
            float f0, f1; upk2(c0, f0, f1);
            hl[s] = fast_tanh(uc[s] + bias + f0 + f1);
        }
#pragma unroll
        for (int s = 0; s < 8; ++s) sHf[w][nxt][s][lane] = hl[s];
        __syncwarp();
#pragma unroll
        for (int s = 0; s < 8; ++s) { uc[s] = un[s]; un[s] = ur[s]; }
    }

    const int off = d * 32 + lane;
#pragma unroll
    for (int s = 0; s < 8; ++s)
        Hout[(size_t)(s0 + s) * 64 + off] = hl[s];
}

// ============================================================================
// Ragged segment mean/min/max over g_h2. One block (64 threads) per batch row.
// ============================================================================
__global__ void seg_kernel(const int* __restrict__ elems)
{
    const int b   = blockIdx.x;
    const int tid = threadIdx.x;   // 0..63
    __shared__ int sred[64];

    int partial = 0;
    for (int i = tid; i < b; i += 64) partial += elems[i];
    sred[tid] = partial;
    __syncthreads();
    for (int s = 32; s; s >>= 1) {
        if (tid < s) sred[tid] += sred[tid + s];
        __syncthreads();
    }
    const int off = sred[0];
    const int cnt = elems[b];

    float s = 0.f, mn = 3.402823466e38f, mx = -3.402823466e38f;
    const float* base = g_h2 + (size_t)off * 64 + tid;
    int r = 0;
    for (; r + 4 <= cnt; r += 4) {
        float v0 = base[(size_t)(r + 0) * 64];
        float v1 = base[(size_t)(r + 1) * 64];
        float v2 = base[(size_t)(r + 2) * 64];
        float v3 = base[(size_t)(r + 3) * 64];
        s += (v0 + v1) + (v2 + v3);
        mn = fminf(mn, fminf(fminf(v0, v1), fminf(v2, v3)));
        mx = fmaxf(mx, fmaxf(fmaxf(v0, v1), fmaxf(v2, v3)));
    }
    for (; r < cnt; ++r) {
        float v = base[(size_t)r * 64];
        s += v; mn = fminf(mn, v); mx = fmaxf(mx, v);
    }
    g_mean[b * 64 + tid] = s / (float)cnt;
    g_min[b * 64 + tid]  = mn;
    g_max[b * 64 + tid]  = mx;
}

// ============================================================================
// Head: concat(305) -> fc1 tanh -> fc2 sigmoid. 128 threads per batch row.
// ============================================================================
__global__ void __launch_bounds__(128) head_kernel(
    const float* __restrict__ normal,
    const float* __restrict__ fc1w, const float* __restrict__ fc1b,
    const float* __restrict__ fc2w, const float* __restrict__ fc2b,
    float* __restrict__ out)
{
    const int b    = blockIdx.x;
    const int tid  = threadIdx.x;
    const int wq   = tid >> 5;
    const int lane = tid & 31;
    __shared__ float xr[FC_IN + 3];
    __shared__ float part[4][32];

    if (tid < 64) {
        xr[tid]       = g_hn[b * 64 + tid];
        xr[113 + tid] = g_mean[b * 64 + tid];
        xr[177 + tid] = g_min[b * 64 + tid];
        xr[241 + tid] = g_max[b * 64 + tid];
    }
    for (int i = tid; i < DNORM; i += 128) xr[64 + i] = normal[b * DNORM + i];
    __syncthreads();

    const int k0 = wq * 76;
    const int k1 = (wq == 3) ? FC_IN : k0 + 76;
    const float* wrow = fc1w + lane * FC_IN;
    float a0 = 0.f, a1 = 0.f, a2 = 0.f, a3 = 0.f;
    int k = k0;
    for (; k + 4 <= k1; k += 4) {
        a0 += xr[k]     * wrow[k];
        a1 += xr[k + 1] * wrow[k + 1];
        a2 += xr[k + 2] * wrow[k + 2];
        a3 += xr[k + 3] * wrow[k + 3];
    }
    for (; k < k1; ++k) a0 += xr[k] * wrow[k];
    part[wq][lane] = (a0 + a1) + (a2 + a3);
    __syncthreads();

    if (wq == 0) {
        float acc = fc1b[lane] + part[0][lane] + part[1][lane] + part[2][lane] + part[3][lane];
        float pv = fast_tanh(acc) * fc2w[lane];
#pragma unroll
        for (int o = 16; o; o >>= 1) pv += __shfl_xor_sync(0xffffffffu, pv, o);
        if (lane == 0) out[b] = fast_sigmoid(pv + fc2b[0]);
    }
}

// ============================================================================
// kernel_launch
// ============================================================================
extern "C" void kernel_launch(void* const* d_in, const int* in_sizes, int n_in,
                              void* d_out, int out_size)
{
    const float* normal   = (const float*)d_in[0];
    const float* text     = (const float*)d_in[1];
    const float* timeline = (const float*)d_in[2];

    const int* elems;
    int base;
    if (in_sizes[3] == BATCH) { elems = (const int*)d_in[3]; base = 4; }
    else                      { elems = (const int*)d_in[n_in - 1]; base = 3; }

    const float* r1[8];
    const float* r2[8];
    for (int i = 0; i < 8; ++i) r1[i] = (const float*)d_in[base + i];
    for (int i = 0; i < 8; ++i) r2[i] = (const float*)d_in[base + 8 + i];
    const float* fc1w = (const float*)d_in[base + 16];
    const float* fc1b = (const float*)d_in[base + 17];
    const float* fc2w = (const float*)d_in[base + 18];
    const float* fc2b = (const float*)d_in[base + 19];
    // per dir: wi, wh, bi, bh ; fwd then bwd

    float* hn; cudaGetSymbolAddress((void**)&hn, g_hn);
    float* h2; cudaGetSymbolAddress((void**)&h2, g_h2);
    float* u1; cudaGetSymbolAddress((void**)&u1, g_u1);
    float* u2; cudaGetSymbolAddress((void**)&u2, g_u2);

    // 1. convert Wih to bf16 hi/lo (model 0 = timeline, 1 = text)
    setup_w_kernel<<<1, 256>>>(r2[0], r2[4], r1[0], r1[4]);

    // 2. tensor-core input GEMM (TMA bulk in/out): 16384 + 512 CTAs
    const int tlG = (NTL * TTL) / GEMM_ROWS;      // 16384
    const int txG = (BATCH * TTEXT) / GEMM_ROWS;  // 512
    gemm_u_kernel<<<tlG + txG, 128>>>(timeline, u2, text, u1, tlG);

    // 3. recurrence: warp = (8 seqs, 1 dir), 4 warps/block
    const int tlB = (NTL / 8 * 2) / 4;     // 2048 blocks
    const int txB = (BATCH / 8 * 2) / 4;   // 32 blocks
    rec_kernel<<<tlB + txB, 128>>>(
        tlB,
        u2, h2, TTL, r2[1], r2[5], r2[2], r2[3], r2[6], r2[7],
        u1, hn, TTEXT, r1[1], r1[5], r1[2], r1[3], r1[6], r1[7]);

    seg_kernel<<<BATCH, 64>>>(elems);

    head_kernel<<<BATCH, 128>>>(normal, fc1w, fc1b, fc2w, fc2b, (float*)d_out);
}

// round 13
// speedup vs baseline: 1.0955x; 1.0095x over previous
#include <cuda_runtime.h>
#include <cuda_bf16.h>
#include <math.h>
#include <stdint.h>

// Problem constants (fixed by setup_inputs)
#define BATCH   512
#define TTEXT   64
#define EDIM    50
#define HDIM    32
#define NTL     32768
#define TTL     32
#define DNORM   49
#define FC_IN   305   // 64 + 49 + 64 + 64 + 64
#define GEMM_ROWS 64  // rows per GEMM tile
#define TL_TILES  16384   // NTL*TTL/GEMM_ROWS
#define TX_TILES  512     // BATCH*TTEXT/GEMM_ROWS
#define TPC       16      // tiles per persistent CTA
#define GEMM_GRID ((TL_TILES + TX_TILES) / TPC)   // 1056

typedef unsigned long long u64t;

// -------- device scratch (static; no runtime allocation) --------
__device__ float g_hn[BATCH * 64];            // text biRNN final hidden [B, 2H]
__device__ float g_h2[NTL * 64];              // timeline biRNN final hidden [N, 2H]
__device__ float g_mean[BATCH * 64];
__device__ float g_min[BATCH * 64];
__device__ float g_max[BATCH * 64];
__device__ float g_u2[(size_t)NTL * TTL * 64];   // u = x@Wih^T, timeline (268 MB)
__device__ float g_u1[BATCH * TTEXT * 64];       // u for text (8 MB)
__device__ __nv_bfloat16 g_wh[2][64][72];        // Wih bf16-hi  [model][n][k]
__device__ __nv_bfloat16 g_wl[2][64][72];        // Wih bf16-lo

// ---------------- packed f32x2 helpers ----------------
__device__ __forceinline__ u64t pk2(float a, float b) {
    u64t r; asm("mov.b64 %0,{%1,%2};" : "=l"(r) : "f"(a), "f"(b)); return r;
}
__device__ __forceinline__ void upk2(u64t v, float& a, float& b) {
    asm("mov.b64 {%0,%1},%2;" : "=f"(a), "=f"(b) : "l"(v));
}
__device__ __forceinline__ u64t fma2(u64t a, u64t b, u64t c) {
    u64t d; asm("fma.rn.f32x2 %0,%1,%2,%3;" : "=l"(d) : "l"(a), "l"(b), "l"(c)); return d;
}
__device__ __forceinline__ u64t add2(u64t a, u64t b) {
    u64t d; asm("add.rn.f32x2 %0,%1,%2;" : "=l"(d) : "l"(a), "l"(b)); return d;
}

// tanh(x) = 1 - 2/(e^{2x}+1) via MUFU ex2/rcp (rel err ~1e-6)
__device__ __forceinline__ float fast_tanh(float x) {
    float e, r;
    asm("ex2.approx.f32 %0,%1;" : "=f"(e) : "f"(x * 2.8853900817779268f));
    asm("rcp.approx.f32 %0,%1;" : "=f"(r) : "f"(e + 1.0f));
    return fmaf(-2.0f, r, 1.0f);
}
__device__ __forceinline__ float fast_sigmoid(float x) {
    float e, r;
    asm("ex2.approx.f32 %0,%1;" : "=f"(e) : "f"(-x * 1.4426950408889634f));
    asm("rcp.approx.f32 %0,%1;" : "=f"(r) : "f"(e + 1.0f));
    return r;
}

// ---------------- TMA 1D bulk + mbarrier helpers ----------------
__device__ __forceinline__ uint32_t smem_u32(const void* p) {
    return (uint32_t)__cvta_generic_to_shared(p);
}
__device__ __forceinline__ void mbar_init(uint32_t mb, uint32_t cnt) {
    asm volatile("mbarrier.init.shared.b64 [%0], %1;" :: "r"(mb), "r"(cnt) : "memory");
}
__device__ __forceinline__ void mbar_expect_tx(uint32_t mb, uint32_t bytes) {
    asm volatile("mbarrier.arrive.expect_tx.shared.b64 _, [%0], %1;"
                 :: "r"(mb), "r"(bytes) : "memory");
}
__device__ __forceinline__ void mbar_wait(uint32_t mb, uint32_t parity) {
    asm volatile(
        "{\n\t.reg .pred P;\n\t"
        "W%=:\n\t"
        "mbarrier.try_wait.parity.acquire.cta.shared::cta.b64 P, [%0], %1, 0x989680;\n\t"
        "@!P bra W%=;\n\t}"
        :: "r"(mb), "r"(parity) : "memory");
}
__device__ __forceinline__ void tma_bulk_g2s(uint32_t dst, const void* src,
                                             uint32_t bytes, uint32_t mb) {
    asm volatile(
        "cp.async.bulk.shared::cta.global.mbarrier::complete_tx::bytes [%0], [%1], %2, [%3];"
        :: "r"(dst), "l"(src), "r"(bytes), "r"(mb) : "memory");
}
__device__ __forceinline__ void tma_bulk_s2g_commit(void* dst, uint32_t src, uint32_t bytes) {
    asm volatile("cp.async.bulk.global.shared::cta.bulk_group [%0], [%1], %2;"
                 :: "l"(dst), "r"(src), "r"(bytes) : "memory");
    asm volatile("cp.async.bulk.commit_group;" ::: "memory");
}
__device__ __forceinline__ void tma_bulk_store_wait0() {
    asm volatile("cp.async.bulk.wait_group 0;" ::: "memory");
}

// mma.sync m16n8k16 row.col f32.bf16.bf16.f32, D += A*B
#define MMA16816(C, A, B0, B1) \
    asm volatile("mma.sync.aligned.m16n8k16.row.col.f32.bf16.bf16.f32 " \
        "{%0,%1,%2,%3}, {%4,%5,%6,%7}, {%8,%9}, {%0,%1,%2,%3};" \
        : "+f"((C)[0]), "+f"((C)[1]), "+f"((C)[2]), "+f"((C)[3]) \
        : "r"((A)[0]), "r"((A)[1]), "r"((A)[2]), "r"((A)[3]), "r"(B0), "r"(B1))

// ============================================================================
// Setup: convert Wih (both models, both dirs) to bf16 hi/lo, layout
// [n=dir*32+unit][k padded to 72, zeros beyond 50]. One tiny launch.
// ============================================================================
__global__ void setup_w_kernel(const float* __restrict__ l_Wif, const float* __restrict__ l_Wib,
                               const float* __restrict__ t_Wif, const float* __restrict__ t_Wib)
{
    for (int idx = threadIdx.x; idx < 2 * 64 * 72; idx += blockDim.x) {
        int m = idx / (64 * 72);
        int rem = idx % (64 * 72);
        int n = rem / 72, k = rem % 72;
        int d = n >> 5, unit = n & 31;
        const float* W = (m == 0) ? (d ? l_Wib : l_Wif) : (d ? t_Wib : t_Wif);
        float v = (k < EDIM) ? W[unit * EDIM + k] : 0.f;
        __nv_bfloat16 h = __float2bfloat16_rn(v);
        float r = v - __bfloat162float(h);
        g_wh[m][n][k] = h;
        g_wl[m][n][k] = __float2bfloat16_rn(r);
    }
}

// ============================================================================
// Persistent tensor-core GEMM: U = X @ Wih^T (bf16 split: Ah*Bh+Ah*Bl+Al*Bh).
// Each CTA processes TPC=16 consecutive 64-row tiles with:
//   - double-buffered TMA bulk g2s, distance-2 prefetch (DRAM latency hidden)
//   - A-fragment conversion fp32->bf16 hi/lo IN REGISTERS (no smem staging)
//   - one bulk s2g store per tile (commit; drained under next tile's mma)
// Tiles [0, TL_TILES) -> timeline, rest -> text.
// ============================================================================
__global__ void __launch_bounds__(128) gemm_u_kernel(
    const float* __restrict__ Xl, float* __restrict__ Ul,
    const float* __restrict__ Xt, float* __restrict__ Ut)
{
    __shared__ __align__(16) float xa[2][GEMM_ROWS * EDIM];   // 2 x 12800 B
    __shared__ __align__(16) float uo[GEMM_ROWS * 64];        // 16384 B
    __shared__ __align__(8)  u64t mbar[2];

    const int tid = threadIdx.x, w = tid >> 5, lane = tid & 31;
    const int g = lane >> 2, t = lane & 3;
    const int m0 = w * 16;
    const int tile0 = blockIdx.x * TPC;

    const uint32_t mb0 = smem_u32(&mbar[0]);
    const uint32_t mb1 = smem_u32(&mbar[1]);
    if (tid == 0) { mbar_init(mb0, 1); mbar_init(mb1, 1); }
    __syncthreads();

    // prologue: tiles tile0 -> buf0, tile0+1 -> buf1
    if (tid == 0) {
#pragma unroll
        for (int p = 0; p < 2; ++p) {
            const int tt = tile0 + p;
            const float* X = (tt < TL_TILES)
                ? Xl + (size_t)tt * GEMM_ROWS * EDIM
                : Xt + (size_t)(tt - TL_TILES) * GEMM_ROWS * EDIM;
            const uint32_t mb = p ? mb1 : mb0;
            mbar_expect_tx(mb, GEMM_ROWS * EDIM * 4);
            tma_bulk_g2s(smem_u32(&xa[p][0]), X, GEMM_ROWS * EDIM * 4, mb);
        }
    }

    for (int i = 0; i < TPC; ++i) {
        const int cur = i & 1;
        const int tt  = tile0 + i;
        const int mdl = (tt < TL_TILES) ? 0 : 1;
        float* U = (tt < TL_TILES)
            ? Ul + (size_t)tt * GEMM_ROWS * 64
            : Ut + (size_t)(tt - TL_TILES) * GEMM_ROWS * 64;

        // wait for this tile's x; parity = use-count of this buffer mod 2
        mbar_wait(cur ? mb1 : mb0, (uint32_t)((i >> 1) & 1));

        // ---- A fragments: load fp32 pairs from xa, convert hi/lo in regs ----
        uint32_t Ah[4][4], Al[4][4];
        const float* xb = &xa[cur][0];
#pragma unroll
        for (int kt = 0; kt < 4; ++kt) {
            const int ko = kt * 16 + t * 2;
#pragma unroll
            for (int half = 0; half < 2; ++half) {     // k pair at ko, ko+8
                const int p = ko + half * 8;
                const bool valid = (p < EDIM);
#pragma unroll
                for (int rr = 0; rr < 2; ++rr) {       // rows g, g+8
                    const int row = m0 + g + rr * 8;
                    float2 v = valid ? *(const float2*)(xb + row * EDIM + p)
                                     : make_float2(0.f, 0.f);
                    __nv_bfloat162 h2 = __floats2bfloat162_rn(v.x, v.y);
                    float2 hb = __bfloat1622float2(h2);
                    __nv_bfloat162 l2 = __floats2bfloat162_rn(v.x - hb.x, v.y - hb.y);
                    Ah[kt][rr + half * 2] = *(uint32_t*)&h2;
                    Al[kt][rr + half * 2] = *(uint32_t*)&l2;
                }
            }
        }
        __syncthreads();   // all threads done reading xa[cur]

        // prefetch tile i+2 into the buffer we just drained
        if (tid == 0 && i + 2 < TPC) {
            const int tn = tile0 + i + 2;
            const float* X = (tn < TL_TILES)
                ? Xl + (size_t)tn * GEMM_ROWS * EDIM
                : Xt + (size_t)(tn - TL_TILES) * GEMM_ROWS * EDIM;
            const uint32_t mb = cur ? mb1 : mb0;
            mbar_expect_tx(mb, GEMM_ROWS * EDIM * 4);
            tma_bulk_g2s(smem_u32(&xa[cur][0]), X, GEMM_ROWS * EDIM * 4, mb);
        }

        const __nv_bfloat16* WH = &g_wh[mdl][0][0];
        const __nv_bfloat16* WL = &g_wl[mdl][0][0];

        // previous tile's U store must drain before we overwrite uo
        if (tid == 0) tma_bulk_store_wait0();
        __syncthreads();

#pragma unroll
        for (int nc = 0; nc < 4; ++nc) {       // 16 output cols per chunk
            float c[2][4];
#pragma unroll
            for (int nt = 0; nt < 2; ++nt) { c[nt][0]=c[nt][1]=c[nt][2]=c[nt][3]=0.f; }
#pragma unroll
            for (int kt = 0; kt < 4; ++kt) {
                const int ko = kt * 16 + t * 2;
#pragma unroll
                for (int nt = 0; nt < 2; ++nt) {
                    const int n = nc * 16 + nt * 8 + g;
                    uint32_t bh0 = *(const uint32_t*)(WH + n * 72 + ko);
                    uint32_t bh1 = *(const uint32_t*)(WH + n * 72 + ko + 8);
                    uint32_t bl0 = *(const uint32_t*)(WL + n * 72 + ko);
                    uint32_t bl1 = *(const uint32_t*)(WL + n * 72 + ko + 8);
                    MMA16816(c[nt], Ah[kt], bh0, bh1);
                    MMA16816(c[nt], Ah[kt], bl0, bl1);
                    MMA16816(c[nt], Al[kt], bh0, bh1);
                }
            }
#pragma unroll
            for (int nt = 0; nt < 2; ++nt) {
                const int col = nc * 16 + nt * 8 + t * 2;
                const int row = m0 + g;
                *(float2*)(uo + row * 64 + col)       = make_float2(c[nt][0], c[nt][1]);
                *(float2*)(uo + (row + 8) * 64 + col) = make_float2(c[nt][2], c[nt][3]);
            }
        }
        __syncthreads();

        if (tid == 0) {
            asm volatile("fence.proxy.async;" ::: "memory");
            tma_bulk_s2g_commit(U, smem_u32(uo), GEMM_ROWS * 64 * 4);
        }
    }
    if (tid == 0) tma_bulk_store_wait0();
}

// ============================================================================
// Recurrence: h_t = tanh(u_t + bias + h_{t-1}·Whh^T), final h only.
// One warp = (8 sequences, 1 direction); lane = hidden unit. Whh in registers
// (natural pairs), u via coalesced LDG.32 with distance-2 register prefetch,
// h double-buffered in smem (LDS.128 broadcast).
// blocks [0, tlBlocks) -> timeline, rest -> text.
// ============================================================================
__global__ void __launch_bounds__(128, 4) rec_kernel(
    int tlBlocks,
    const float* __restrict__ U2, float* __restrict__ H2o, int Tl,
    const float* __restrict__ l_Whf, const float* __restrict__ l_Whb,
    const float* __restrict__ l_bif, const float* __restrict__ l_bhf,
    const float* __restrict__ l_bib, const float* __restrict__ l_bhb,
    const float* __restrict__ U1, float* __restrict__ H1o, int Tt,
    const float* __restrict__ t_Whf, const float* __restrict__ t_Whb,
    const float* __restrict__ t_bif, const float* __restrict__ t_bhf,
    const float* __restrict__ t_bib, const float* __restrict__ t_bhb)
{
    __shared__ __align__(16) float sHf[4][2][8][HDIM];   // 8 KB

    const int tid = threadIdx.x, w = tid >> 5, lane = tid & 31;
    const bool isTL = (int)blockIdx.x < tlBlocks;
    const int  blk  = isTL ? blockIdx.x : (blockIdx.x - tlBlocks);
    const float* U  = isTL ? U2 : U1;
    float*    Hout  = isTL ? H2o : H1o;
    const int T     = isTL ? Tl : Tt;

    const int gw = blk * 4 + w;
    const int gI = gw >> 1;          // group of 8 sequences
    const int d  = gw & 1;           // direction

    const float* Wh = isTL ? (d ? l_Whb : l_Whf) : (d ? t_Whb : t_Whf);
    const float* bi = isTL ? (d ? l_bib : l_bif) : (d ? t_bib : t_bif);
    const float* bh = isTL ? (d ? l_bhb : l_bhf) : (d ? t_bhb : t_bhf);

    u64t wh[16];   // natural pairs {Wh[l][2i], Wh[l][2i+1]}
    {
        const u64t* Wh2 = (const u64t*)(Wh + lane * HDIM);
#pragma unroll
        for (int i = 0; i < 16; ++i) wh[i] = Wh2[i];
    }
    const float bias = bi[lane] + bh[lane];

    const int s0  = 8 * gI;
    const int sgn = d ? -64 : 64;
    const float* base = U + ((size_t)s0 * T + (d ? T - 1 : 0)) * 64 + d * 32 + lane;
    int sOff[8];
#pragma unroll
    for (int s = 0; s < 8; ++s) sOff[s] = s * T * 64;

    float uc[8], un[8];
#pragma unroll
    for (int s = 0; s < 8; ++s) uc[s] = base[sOff[s]];
#pragma unroll
    for (int s = 0; s < 8; ++s) un[s] = (T > 1) ? base[sOff[s] + sgn] : 0.f;
    const float* pf = base + 2 * sgn;

#pragma unroll
    for (int s = 0; s < 8; ++s) sHf[w][0][s][lane] = 0.f;
    __syncwarp();

    float hl[8];
#pragma unroll
    for (int s = 0; s < 8; ++s) hl[s] = 0.f;

    for (int t = 0; t < T; ++t) {
        const int cur = t & 1, nxt = cur ^ 1;

        // prefetch u_{t+2} (2-iteration latency slack)
        float ur[8];
        if (t + 2 < T) {
#pragma unroll
            for (int s = 0; s < 8; ++s) ur[s] = pf[sOff[s]];
        } else {
#pragma unroll
            for (int s = 0; s < 8; ++s) ur[s] = 0.f;
        }
        pf += sgn;

        // recurrence for step t
#pragma unroll
        for (int s = 0; s < 8; ++s) {
            const ulonglong2* h4 = (const ulonglong2*)&sHf[w][cur][s][0];
            u64t c0 = 0ull, c1 = 0ull;
#pragma unroll
            for (int i = 0; i < 8; ++i) {
                ulonglong2 hh = h4[i];             // LDS.128 broadcast
                c0 = fma2(hh.x, wh[2 * i],     c0);
                c1 = fma2(hh.y, wh[2 * i + 1], c1);
            }
            c0 = add2(c0, c1);
            float f0, f1; upk2(c0, f0, f1);
            hl[s] = fast_tanh(uc[s] + bias + f0 + f1);
        }
#pragma unroll
        for (int s = 0; s < 8; ++s) sHf[w][nxt][s][lane] = hl[s];
        __syncwarp();
#pragma unroll
        for (int s = 0; s < 8; ++s) { uc[s] = un[s]; un[s] = ur[s]; }
    }

    const int off = d * 32 + lane;
#pragma unroll
    for (int s = 0; s < 8; ++s)
        Hout[(size_t)(s0 + s) * 64 + off] = hl[s];
}

// ============================================================================
// Ragged segment mean/min/max over g_h2. One block (64 threads) per batch row.
// ============================================================================
__global__ void seg_kernel(const int* __restrict__ elems)
{
    const int b   = blockIdx.x;
    const int tid = threadIdx.x;   // 0..63
    __shared__ int sred[64];

    int partial = 0;
    for (int i = tid; i < b; i += 64) partial += elems[i];
    sred[tid] = partial;
    __syncthreads();
    for (int s = 32; s; s >>= 1) {
        if (tid < s) sred[tid] += sred[tid + s];
        __syncthreads();
    }
    const int off = sred[0];
    const int cnt = elems[b];

    float s = 0.f, mn = 3.402823466e38f, mx = -3.402823466e38f;
    const float* base = g_h2 + (size_t)off * 64 + tid;
    int r = 0;
    for (; r + 4 <= cnt; r += 4) {
        float v0 = base[(size_t)(r + 0) * 64];
        float v1 = base[(size_t)(r + 1) * 64];
        float v2 = base[(size_t)(r + 2) * 64];
        float v3 = base[(size_t)(r + 3) * 64];
        s += (v0 + v1) + (v2 + v3);
        mn = fminf(mn, fminf(fminf(v0, v1), fminf(v2, v3)));
        mx = fmaxf(mx, fmaxf(fmaxf(v0, v1), fmaxf(v2, v3)));
    }
    for (; r < cnt; ++r) {
        float v = base[(size_t)r * 64];
        s += v; mn = fminf(mn, v); mx = fmaxf(mx, v);
    }
    g_mean[b * 64 + tid] = s / (float)cnt;
    g_min[b * 64 + tid]  = mn;
    g_max[b * 64 + tid]  = mx;
}

// ============================================================================
// Head: concat(305) -> fc1 tanh -> fc2 sigmoid. 128 threads per batch row.
// ============================================================================
__global__ void __launch_bounds__(128) head_kernel(
    const float* __restrict__ normal,
    const float* __restrict__ fc1w, const float* __restrict__ fc1b,
    const float* __restrict__ fc2w, const float* __restrict__ fc2b,
    float* __restrict__ out)
{
    const int b    = blockIdx.x;
    const int tid  = threadIdx.x;
    const int wq   = tid >> 5;
    const int lane = tid & 31;
    __shared__ float xr[FC_IN + 3];
    __shared__ float part[4][32];

    if (tid < 64) {
        xr[tid]       = g_hn[b * 64 + tid];
        xr[113 + tid] = g_mean[b * 64 + tid];
        xr[177 + tid] = g_min[b * 64 + tid];
        xr[241 + tid] = g_max[b * 64 + tid];
    }
    for (int i = tid; i < DNORM; i += 128) xr[64 + i] = normal[b * DNORM + i];
    __syncthreads();

    const int k0 = wq * 76;
    const int k1 = (wq == 3) ? FC_IN : k0 + 76;
    const float* wrow = fc1w + lane * FC_IN;
    float a0 = 0.f, a1 = 0.f, a2 = 0.f, a3 = 0.f;
    int k = k0;
    for (; k + 4 <= k1; k += 4) {
        a0 += xr[k]     * wrow[k];
        a1 += xr[k + 1] * wrow[k + 1];
        a2 += xr[k + 2] * wrow[k + 2];
        a3 += xr[k + 3] * wrow[k + 3];
    }
    for (; k < k1; ++k) a0 += xr[k] * wrow[k];
    part[wq][lane] = (a0 + a1) + (a2 + a3);
    __syncthreads();

    if (wq == 0) {
        float acc = fc1b[lane] + part[0][lane] + part[1][lane] + part[2][lane] + part[3][lane];
        float pv = fast_tanh(acc) * fc2w[lane];
#pragma unroll
        for (int o = 16; o; o >>= 1) pv += __shfl_xor_sync(0xffffffffu, pv, o);
        if (lane == 0) out[b] = fast_sigmoid(pv + fc2b[0]);
    }
}

// ============================================================================
// kernel_launch
// ============================================================================
extern "C" void kernel_launch(void* const* d_in, const int* in_sizes, int n_in,
                              void* d_out, int out_size)
{
    const float* normal   = (const float*)d_in[0];
    const float* text     = (const float*)d_in[1];
    const float* timeline = (const float*)d_in[2];

    const int* elems;
    int base;
    if (in_sizes[3] == BATCH) { elems = (const int*)d_in[3]; base = 4; }
    else                      { elems = (const int*)d_in[n_in - 1]; base = 3; }

    const float* r1[8];
    const float* r2[8];
    for (int i = 0; i < 8; ++i) r1[i] = (const float*)d_in[base + i];
    for (int i = 0; i < 8; ++i) r2[i] = (const float*)d_in[base + 8 + i];
    const float* fc1w = (const float*)d_in[base + 16];
    const float* fc1b = (const float*)d_in[base + 17];
    const float* fc2w = (const float*)d_in[base + 18];
    const float* fc2b = (const float*)d_in[base + 19];
    // per dir: wi, wh, bi, bh ; fwd then bwd

    float* hn; cudaGetSymbolAddress((void**)&hn, g_hn);
    float* h2; cudaGetSymbolAddress((void**)&h2, g_h2);
    float* u1; cudaGetSymbolAddress((void**)&u1, g_u1);
    float* u2; cudaGetSymbolAddress((void**)&u2, g_u2);

    // 1. convert Wih to bf16 hi/lo (model 0 = timeline, 1 = text)
    setup_w_kernel<<<1, 256>>>(r2[0], r2[4], r1[0], r1[4]);

    // 2. persistent tensor-core input GEMM (double-buffered TMA)
    gemm_u_kernel<<<GEMM_GRID, 128>>>(timeline, u2, text, u1);

    // 3. recurrence: warp = (8 seqs, 1 dir), 4 warps/block
    const int tlB = (NTL / 8 * 2) / 4;     // 2048 blocks
    const int txB = (BATCH / 8 * 2) / 4;   // 32 blocks
    rec_kernel<<<tlB + txB, 128>>>(
        tlB,
        u2, h2, TTL, r2[1], r2[5], r2[2], r2[3], r2[6], r2[7],
        u1, hn, TTEXT, r1[1], r1[5], r1[2], r1[3], r1[6], r1[7]);

    seg_kernel<<<BATCH, 64>>>(elems);

    head_kernel<<<BATCH, 128>>>(normal, fc1w, fc1b, fc2w, fc2b, (float*)d_out);
}

// round 14
// speedup vs baseline: 1.3538x; 1.2358x over previous
#include <cuda_runtime.h>
#include <cuda_bf16.h>
#include <math.h>
#include <stdint.h>

// Problem constants (fixed by setup_inputs)
#define BATCH   512
#define TTEXT   64
#define EDIM    50
#define HDIM    32
#define NTL     32768
#define TTL     32
#define DNORM   49
#define FC_IN   305   // 64 + 49 + 64 + 64 + 64
#define GEMM_ROWS 64  // rows per GEMM tile
#define TL_TILES  16384   // NTL*TTL/GEMM_ROWS
#define TX_TILES  512     // BATCH*TTEXT/GEMM_ROWS
#define TPC       16      // tiles per persistent CTA
#define GEMM_GRID ((TL_TILES + TX_TILES) / TPC)   // 1056
// rec_tc grid: tl fwd 512 + tl bwd 512 + tx fwd 8 + tx bwd 8
#define REC_TL_CTAS 512
#define REC_TX_CTAS 8
#define REC_GRID (2 * REC_TL_CTAS + 2 * REC_TX_CTAS)   // 1040

typedef unsigned long long u64t;

// -------- device scratch (static; no runtime allocation) --------
__device__ float g_hn[BATCH * 64];            // text biRNN final hidden [B, 2H]
__device__ float g_h2[NTL * 64];              // timeline biRNN final hidden [N, 2H]
__device__ float g_mean[BATCH * 64];
__device__ float g_min[BATCH * 64];
__device__ float g_max[BATCH * 64];
__device__ float g_u2[(size_t)NTL * TTL * 64];   // u = x@Wih^T + bias, timeline
__device__ float g_u1[BATCH * TTEXT * 64];       // u for text
__device__ __nv_bfloat16 g_wh[2][64][72];        // Wih bf16-hi  [model][n][k]
__device__ __nv_bfloat16 g_wl[2][64][72];        // Wih bf16-lo
__device__ __nv_bfloat16 g_whh_h[2][2][HDIM * HDIM];  // Whh hi [model][dir][n*32+k]
__device__ __nv_bfloat16 g_whh_l[2][2][HDIM * HDIM];  // Whh lo
__device__ float g_bias[2][64];                  // bi+bh  [model][dir*32+unit]

// tanh(x) = 1 - 2/(e^{2x}+1) via MUFU ex2/rcp (rel err ~1e-6)
__device__ __forceinline__ float fast_tanh(float x) {
    float e, r;
    asm("ex2.approx.f32 %0,%1;" : "=f"(e) : "f"(x * 2.8853900817779268f));
    asm("rcp.approx.f32 %0,%1;" : "=f"(r) : "f"(e + 1.0f));
    return fmaf(-2.0f, r, 1.0f);
}
__device__ __forceinline__ float fast_sigmoid(float x) {
    float e, r;
    asm("ex2.approx.f32 %0,%1;" : "=f"(e) : "f"(-x * 1.4426950408889634f));
    asm("rcp.approx.f32 %0,%1;" : "=f"(r) : "f"(e + 1.0f));
    return r;
}

// ---------------- TMA 1D bulk + mbarrier helpers ----------------
__device__ __forceinline__ uint32_t smem_u32(const void* p) {
    return (uint32_t)__cvta_generic_to_shared(p);
}
__device__ __forceinline__ void mbar_init(uint32_t mb, uint32_t cnt) {
    asm volatile("mbarrier.init.shared.b64 [%0], %1;" :: "r"(mb), "r"(cnt) : "memory");
}
__device__ __forceinline__ void mbar_expect_tx(uint32_t mb, uint32_t bytes) {
    asm volatile("mbarrier.arrive.expect_tx.shared.b64 _, [%0], %1;"
                 :: "r"(mb), "r"(bytes) : "memory");
}
__device__ __forceinline__ void mbar_wait(uint32_t mb, uint32_t parity) {
    asm volatile(
        "{\n\t.reg .pred P;\n\t"
        "W%=:\n\t"
        "mbarrier.try_wait.parity.acquire.cta.shared::cta.b64 P, [%0], %1, 0x989680;\n\t"
        "@!P bra W%=;\n\t}"
        :: "r"(mb), "r"(parity) : "memory");
}
__device__ __forceinline__ void tma_bulk_g2s(uint32_t dst, const void* src,
                                             uint32_t bytes, uint32_t mb) {
    asm volatile(
        "cp.async.bulk.shared::cta.global.mbarrier::complete_tx::bytes [%0], [%1], %2, [%3];"
        :: "r"(dst), "l"(src), "r"(bytes), "r"(mb) : "memory");
}
__device__ __forceinline__ void tma_bulk_s2g_commit(void* dst, uint32_t src, uint32_t bytes) {
    asm volatile("cp.async.bulk.global.shared::cta.bulk_group [%0], [%1], %2;"
                 :: "l"(dst), "r"(src), "r"(bytes) : "memory");
    asm volatile("cp.async.bulk.commit_group;" ::: "memory");
}
__device__ __forceinline__ void tma_bulk_store_wait0() {
    asm volatile("cp.async.bulk.wait_group 0;" ::: "memory");
}

// mma.sync m16n8k16 row.col f32.bf16.bf16.f32, D += A*B
#define MMA16816(C, A, B0, B1) \
    asm volatile("mma.sync.aligned.m16n8k16.row.col.f32.bf16.bf16.f32 " \
        "{%0,%1,%2,%3}, {%4,%5,%6,%7}, {%8,%9}, {%0,%1,%2,%3};" \
        : "+f"((C)[0]), "+f"((C)[1]), "+f"((C)[2]), "+f"((C)[3]) \
        : "r"((A)[0]), "r"((A)[1]), "r"((A)[2]), "r"((A)[3]), "r"(B0), "r"(B1))

// fp32 pair -> bf16x2 hi + lo residual (in registers)
__device__ __forceinline__ void split_pair(float x, float y, uint32_t& hi, uint32_t& lo) {
    __nv_bfloat162 h2 = __floats2bfloat162_rn(x, y);
    float2 hb = __bfloat1622float2(h2);
    __nv_bfloat162 l2 = __floats2bfloat162_rn(x - hb.x, y - hb.y);
    hi = *(uint32_t*)&h2;
    lo = *(uint32_t*)&l2;
}

// ============================================================================
// Setup: Wih -> bf16 hi/lo [model][n=dir*32+unit][k pad 72];
//        Whh -> bf16 hi/lo [model][dir][n*32+k];  bias[model][dir*32+unit].
// ============================================================================
__global__ void setup_w_kernel(
    const float* __restrict__ l_Wif, const float* __restrict__ l_Wib,
    const float* __restrict__ t_Wif, const float* __restrict__ t_Wib,
    const float* __restrict__ l_Whf, const float* __restrict__ l_Whb,
    const float* __restrict__ t_Whf, const float* __restrict__ t_Whb,
    const float* __restrict__ l_bif, const float* __restrict__ l_bhf,
    const float* __restrict__ l_bib, const float* __restrict__ l_bhb,
    const float* __restrict__ t_bif, const float* __restrict__ t_bhf,
    const float* __restrict__ t_bib, const float* __restrict__ t_bhb)
{
    const int tid = threadIdx.x;
    for (int idx = tid; idx < 2 * 64 * 72; idx += 256) {
        int m = idx / (64 * 72);
        int rem = idx % (64 * 72);
        int n = rem / 72, k = rem % 72;
        int d = n >> 5, unit = n & 31;
        const float* W = (m == 0) ? (d ? l_Wib : l_Wif) : (d ? t_Wib : t_Wif);
        float v = (k < EDIM) ? W[unit * EDIM + k] : 0.f;
        __nv_bfloat16 h = __float2bfloat16_rn(v);
        g_wh[m][n][k] = h;
        g_wl[m][n][k] = __float2bfloat16_rn(v - __bfloat162float(h));
    }
    for (int idx = tid; idx < 2 * 2 * HDIM * HDIM; idx += 256) {
        int m = idx >> 11;
        int rem = idx & 2047;
        int d = rem >> 10;
        int nk = rem & 1023;
        const float* W = (m == 0) ? (d ? l_Whb : l_Whf) : (d ? t_Whb : t_Whf);
        float v = W[nk];   // [n][k] natural row-major: B[k][n] col-major = Whh[n][k]
        __nv_bfloat16 h = __float2bfloat16_rn(v);
        g_whh_h[m][d][nk] = h;
        g_whh_l[m][d][nk] = __float2bfloat16_rn(v - __bfloat162float(h));
    }
    for (int idx = tid; idx < 128; idx += 256) {
        int m = idx >> 6, c = idx & 63, d = (c >> 5) & 1, i = c & 31;
        const float* bi = (m == 0) ? (d ? l_bib : l_bif) : (d ? t_bib : t_bif);
        const float* bh = (m == 0) ? (d ? l_bhb : l_bhf) : (d ? t_bhb : t_bhf);
        g_bias[m][c] = bi[i] + bh[i];
    }
}

// ============================================================================
// Persistent tensor-core GEMM: U = X @ Wih^T + bias (bf16 split).
// TPC tiles per CTA, double-buffered TMA bulk in, bulk out. (unchanged R13
// except bias folded into epilogue.)
// ============================================================================
__global__ void __launch_bounds__(128) gemm_u_kernel(
    const float* __restrict__ Xl, float* __restrict__ Ul,
    const float* __restrict__ Xt, float* __restrict__ Ut)
{
    __shared__ __align__(16) float xa[2][GEMM_ROWS * EDIM];
    __shared__ __align__(16) float uo[GEMM_ROWS * 64];
    __shared__ __align__(8)  u64t mbar[2];

    const int tid = threadIdx.x, w = tid >> 5, lane = tid & 31;
    const int g = lane >> 2, t = lane & 3;
    const int m0 = w * 16;
    const int tile0 = blockIdx.x * TPC;

    const uint32_t mb0 = smem_u32(&mbar[0]);
    const uint32_t mb1 = smem_u32(&mbar[1]);
    if (tid == 0) { mbar_init(mb0, 1); mbar_init(mb1, 1); }
    __syncthreads();

    if (tid == 0) {
#pragma unroll
        for (int p = 0; p < 2; ++p) {
            const int tt = tile0 + p;
            const float* X = (tt < TL_TILES)
                ? Xl + (size_t)tt * GEMM_ROWS * EDIM
                : Xt + (size_t)(tt - TL_TILES) * GEMM_ROWS * EDIM;
            const uint32_t mb = p ? mb1 : mb0;
            mbar_expect_tx(mb, GEMM_ROWS * EDIM * 4);
            tma_bulk_g2s(smem_u32(&xa[p][0]), X, GEMM_ROWS * EDIM * 4, mb);
        }
    }

    for (int i = 0; i < TPC; ++i) {
        const int cur = i & 1;
        const int tt  = tile0 + i;
        const int mdl = (tt < TL_TILES) ? 0 : 1;
        float* U = (tt < TL_TILES)
            ? Ul + (size_t)tt * GEMM_ROWS * 64
            : Ut + (size_t)(tt - TL_TILES) * GEMM_ROWS * 64;

        mbar_wait(cur ? mb1 : mb0, (uint32_t)((i >> 1) & 1));

        uint32_t Ah[4][4], Al[4][4];
        const float* xb = &xa[cur][0];
#pragma unroll
        for (int kt = 0; kt < 4; ++kt) {
            const int ko = kt * 16 + t * 2;
#pragma unroll
            for (int half = 0; half < 2; ++half) {
                const int p = ko + half * 8;
                const bool valid = (p < EDIM);
#pragma unroll
                for (int rr = 0; rr < 2; ++rr) {
                    const int row = m0 + g + rr * 8;
                    float2 v = valid ? *(const float2*)(xb + row * EDIM + p)
                                     : make_float2(0.f, 0.f);
                    split_pair(v.x, v.y, Ah[kt][rr + half * 2], Al[kt][rr + half * 2]);
                }
            }
        }
        __syncthreads();

        if (tid == 0 && i + 2 < TPC) {
            const int tn = tile0 + i + 2;
            const float* X = (tn < TL_TILES)
                ? Xl + (size_t)tn * GEMM_ROWS * EDIM
                : Xt + (size_t)(tn - TL_TILES) * GEMM_ROWS * EDIM;
            const uint32_t mb = cur ? mb1 : mb0;
            mbar_expect_tx(mb, GEMM_ROWS * EDIM * 4);
            tma_bulk_g2s(smem_u32(&xa[cur][0]), X, GEMM_ROWS * EDIM * 4, mb);
        }

        const __nv_bfloat16* WH = &g_wh[mdl][0][0];
        const __nv_bfloat16* WL = &g_wl[mdl][0][0];

        if (tid == 0) tma_bulk_store_wait0();
        __syncthreads();

#pragma unroll
        for (int nc = 0; nc < 4; ++nc) {
            float c[2][4];
#pragma unroll
            for (int nt = 0; nt < 2; ++nt) { c[nt][0]=c[nt][1]=c[nt][2]=c[nt][3]=0.f; }
#pragma unroll
            for (int kt = 0; kt < 4; ++kt) {
                const int ko = kt * 16 + t * 2;
#pragma unroll
                for (int nt = 0; nt < 2; ++nt) {
                    const int n = nc * 16 + nt * 8 + g;
                    uint32_t bh0 = *(const uint32_t*)(WH + n * 72 + ko);
                    uint32_t bh1 = *(const uint32_t*)(WH + n * 72 + ko + 8);
                    uint32_t bl0 = *(const uint32_t*)(WL + n * 72 + ko);
                    uint32_t bl1 = *(const uint32_t*)(WL + n * 72 + ko + 8);
                    MMA16816(c[nt], Ah[kt], bh0, bh1);
                    MMA16816(c[nt], Ah[kt], bl0, bl1);
                    MMA16816(c[nt], Al[kt], bh0, bh1);
                }
            }
#pragma unroll
            for (int nt = 0; nt < 2; ++nt) {
                const int col = nc * 16 + nt * 8 + t * 2;
                const int row = m0 + g;
                float2 bv = *(const float2*)(&g_bias[mdl][col]);   // fold bias here
                *(float2*)(uo + row * 64 + col)       = make_float2(c[nt][0] + bv.x, c[nt][1] + bv.y);
                *(float2*)(uo + (row + 8) * 64 + col) = make_float2(c[nt][2] + bv.x, c[nt][3] + bv.y);
            }
        }
        __syncthreads();

        if (tid == 0) {
            asm volatile("fence.proxy.async;" ::: "memory");
            tma_bulk_s2g_commit(U, smem_u32(uo), GEMM_ROWS * 64 * 4);
        }
    }
    if (tid == 0) tma_bulk_store_wait0();
}

// ============================================================================
// Tensor-core recurrence: H_t = tanh(U_t + H_{t-1} @ Whh^T).
// CTA = 64 same-direction sequences; warp owns 16 (m-tile). M=64,N=32,K=32.
// KEY: D-frags of step t ARE the A-frags of step t+1 (n-tiles {0,1}->k-tile 0,
// {2,3}->k-tile 1; same thread, no shuffles). Whh as register B-frags with
// hi/lo bf16 split (3 mma) -> per-step error ~2^-16. u read as coalesced
// LDG.64 in D-frag layout with distance-1 prefetch. NO smem, NO syncs.
// blocks: [0,512) tl fwd | [512,1024) tl bwd | 16 text CTAs after.
// ============================================================================
__global__ void __launch_bounds__(128) rec_tc_kernel()
{
    const int tid = threadIdx.x, w = tid >> 5, lane = tid & 31;
    const int g = lane >> 2, t4 = lane & 3;
    const int blk = blockIdx.x;

    int mdl, dir, T, seq0;
    const float* U;
    float* Hd;
    if (blk < 2 * REC_TL_CTAS) {
        mdl = 0; T = TTL; U = g_u2; Hd = g_h2;
        dir = blk >> 9;                 // 512 CTAs per direction
        seq0 = (blk & 511) * 64;
    } else {
        mdl = 1; T = TTEXT; U = g_u1; Hd = g_hn;
        const int b = blk - 2 * REC_TL_CTAS;
        dir = b >> 3;                   // 8 CTAs per direction
        seq0 = (b & 7) * 64;
    }

    // Whh B-fragments (hi/lo) -> registers. [kt][nt][reg]
    uint32_t Bh[2][4][2], Bl[2][4][2];
    {
        const __nv_bfloat16* WH = &g_whh_h[mdl][dir][0];
        const __nv_bfloat16* WL = &g_whh_l[mdl][dir][0];
#pragma unroll
        for (int kt = 0; kt < 2; ++kt) {
            const int ko = kt * 16 + t4 * 2;
#pragma unroll
            for (int nt = 0; nt < 4; ++nt) {
                const int n = nt * 8 + g;
                Bh[kt][nt][0] = *(const uint32_t*)(WH + n * HDIM + ko);
                Bh[kt][nt][1] = *(const uint32_t*)(WH + n * HDIM + ko + 8);
                Bl[kt][nt][0] = *(const uint32_t*)(WL + n * HDIM + ko);
                Bl[kt][nt][1] = *(const uint32_t*)(WL + n * HDIM + ko + 8);
            }
        }
    }

    // u pointers: thread covers rows (seq0 + w*16 + g) and +8, cols per n-tile
    const int row = w * 16 + g;                       // 0..63 across warp
    const int off0 = dir * 32 + t4 * 2;
    const int tt0  = dir ? (T - 1) : 0;
    const int sgnf = dir ? -64 : 64;
    const float* p = U + ((size_t)(seq0 + row) * T + tt0) * 64 + off0;
    const size_t rstr = (size_t)8 * T * 64;           // row +8 stride

    // c[nt][j]: j0,j1 = row g cols 2t4,2t4+1 ; j2,j3 = row g+8 (D-frag layout)
    float c[4][4];
#pragma unroll
    for (int nt = 0; nt < 4; ++nt) {
        float2 v0 = *(const float2*)(p + nt * 8);
        float2 v1 = *(const float2*)(p + rstr + nt * 8);
        c[nt][0] = v0.x; c[nt][1] = v0.y; c[nt][2] = v1.x; c[nt][3] = v1.y;
    }

    uint32_t Ah[2][4], Al[2][4];
    for (int t = 0; t < T; ++t) {
        // prefetch u_{t+1}
        float un[4][4];
        const bool more = (t + 1 < T);
        if (more) {
            const float* pn = p + sgnf;
#pragma unroll
            for (int nt = 0; nt < 4; ++nt) {
                float2 v0 = *(const float2*)(pn + nt * 8);
                float2 v1 = *(const float2*)(pn + rstr + nt * 8);
                un[nt][0] = v0.x; un[nt][1] = v0.y; un[nt][2] = v1.x; un[nt][3] = v1.y;
            }
        }

        // C += H_{t-1} @ Whh^T (skip at t=0: h_{-1}=0)
        if (t > 0) {
#pragma unroll
            for (int kt = 0; kt < 2; ++kt) {
#pragma unroll
                for (int nt = 0; nt < 4; ++nt) {
                    MMA16816(c[nt], Ah[kt], Bh[kt][nt][0], Bh[kt][nt][1]);
                    MMA16816(c[nt], Ah[kt], Bl[kt][nt][0], Bl[kt][nt][1]);
                    MMA16816(c[nt], Al[kt], Bh[kt][nt][0], Bh[kt][nt][1]);
                }
            }
        }

        // tanh elementwise
#pragma unroll
        for (int nt = 0; nt < 4; ++nt) {
#pragma unroll
            for (int j = 0; j < 4; ++j) c[nt][j] = fast_tanh(c[nt][j]);
        }

        if (!more) break;

        // build next A (hi/lo) from D frags: k-tile kt <- n-tiles 2kt, 2kt+1
#pragma unroll
        for (int kt = 0; kt < 2; ++kt) {
            const int na = 2 * kt, nb = 2 * kt + 1;
            split_pair(c[na][0], c[na][1], Ah[kt][0], Al[kt][0]);  // (g,   k 2t4)
            split_pair(c[na][2], c[na][3], Ah[kt][1], Al[kt][1]);  // (g+8, k 2t4)
            split_pair(c[nb][0], c[nb][1], Ah[kt][2], Al[kt][2]);  // (g,   k 2t4+8)
            split_pair(c[nb][2], c[nb][3], Ah[kt][3], Al[kt][3]);  // (g+8, k 2t4+8)
        }

        // shift u
#pragma unroll
        for (int nt = 0; nt < 4; ++nt)
#pragma unroll
            for (int j = 0; j < 4; ++j) c[nt][j] = un[nt][j];
        p += sgnf;
    }

    // c holds final h; store [seq][dir*32 + col]
    float* hb = Hd + (size_t)(seq0 + row) * 64 + off0;
#pragma unroll
    for (int nt = 0; nt < 4; ++nt) {
        *(float2*)(hb + nt * 8)            = make_float2(c[nt][0], c[nt][1]);
        *(float2*)(hb + 8 * 64 + nt * 8)   = make_float2(c[nt][2], c[nt][3]);
    }
}

// ============================================================================
// Ragged segment mean/min/max over g_h2. One block (64 threads) per batch row.
// ============================================================================
__global__ void seg_kernel(const int* __restrict__ elems)
{
    const int b   = blockIdx.x;
    const int tid = threadIdx.x;
    __shared__ int sred[64];

    int partial = 0;
    for (int i = tid; i < b; i += 64) partial += elems[i];
    sred[tid] = partial;
    __syncthreads();
    for (int s = 32; s; s >>= 1) {
        if (tid < s) sred[tid] += sred[tid + s];
        __syncthreads();
    }
    const int off = sred[0];
    const int cnt = elems[b];

    float s = 0.f, mn = 3.402823466e38f, mx = -3.402823466e38f;
    const float* base = g_h2 + (size_t)off * 64 + tid;
    int r = 0;
    for (; r + 4 <= cnt; r += 4) {
        float v0 = base[(size_t)(r + 0) * 64];
        float v1 = base[(size_t)(r + 1) * 64];
        float v2 = base[(size_t)(r + 2) * 64];
        float v3 = base[(size_t)(r + 3) * 64];
        s += (v0 + v1) + (v2 + v3);
        mn = fminf(mn, fminf(fminf(v0, v1), fminf(v2, v3)));
        mx = fmaxf(mx, fmaxf(fmaxf(v0, v1), fmaxf(v2, v3)));
    }
    for (; r < cnt; ++r) {
        float v = base[(size_t)r * 64];
        s += v; mn = fminf(mn, v); mx = fmaxf(mx, v);
    }
    g_mean[b * 64 + tid] = s / (float)cnt;
    g_min[b * 64 + tid]  = mn;
    g_max[b * 64 + tid]  = mx;
}

// ============================================================================
// Head: concat(305) -> fc1 tanh -> fc2 sigmoid. 128 threads per batch row.
// ============================================================================
__global__ void __launch_bounds__(128) head_kernel(
    const float* __restrict__ normal,
    const float* __restrict__ fc1w, const float* __restrict__ fc1b,
    const float* __restrict__ fc2w, const float* __restrict__ fc2b,
    float* __restrict__ out)
{
    const int b    = blockIdx.x;
    const int tid  = threadIdx.x;
    const int wq   = tid >> 5;
    const int lane = tid & 31;
    __shared__ float xr[FC_IN + 3];
    __shared__ float part[4][32];

    if (tid < 64) {
        xr[tid]       = g_hn[b * 64 + tid];
        xr[113 + tid] = g_mean[b * 64 + tid];
        xr[177 + tid] = g_min[b * 64 + tid];
        xr[241 + tid] = g_max[b * 64 + tid];
    }
    for (int i = tid; i < DNORM; i += 128) xr[64 + i] = normal[b * DNORM + i];
    __syncthreads();

    const int k0 = wq * 76;
    const int k1 = (wq == 3) ? FC_IN : k0 + 76;
    const float* wrow = fc1w + lane * FC_IN;
    float a0 = 0.f, a1 = 0.f, a2 = 0.f, a3 = 0.f;
    int k = k0;
    for (; k + 4 <= k1; k += 4) {
        a0 += xr[k]     * wrow[k];
        a1 += xr[k + 1] * wrow[k + 1];
        a2 += xr[k + 2] * wrow[k + 2];
        a3 += xr[k + 3] * wrow[k + 3];
    }
    for (; k < k1; ++k) a0 += xr[k] * wrow[k];
    part[wq][lane] = (a0 + a1) + (a2 + a3);
    __syncthreads();

    if (wq == 0) {
        float acc = fc1b[lane] + part[0][lane] + part[1][lane] + part[2][lane] + part[3][lane];
        float pv = fast_tanh(acc) * fc2w[lane];
#pragma unroll
        for (int o = 16; o; o >>= 1) pv += __shfl_xor_sync(0xffffffffu, pv, o);
        if (lane == 0) out[b] = fast_sigmoid(pv + fc2b[0]);
    }
}

// ============================================================================
// kernel_launch
// ============================================================================
extern "C" void kernel_launch(void* const* d_in, const int* in_sizes, int n_in,
                              void* d_out, int out_size)
{
    const float* normal   = (const float*)d_in[0];
    const float* text     = (const float*)d_in[1];
    const float* timeline = (const float*)d_in[2];

    const int* elems;
    int base;
    if (in_sizes[3] == BATCH) { elems = (const int*)d_in[3]; base = 4; }
    else                      { elems = (const int*)d_in[n_in - 1]; base = 3; }

    const float* r1[8];
    const float* r2[8];
    for (int i = 0; i < 8; ++i) r1[i] = (const float*)d_in[base + i];
    for (int i = 0; i < 8; ++i) r2[i] = (const float*)d_in[base + 8 + i];
    const float* fc1w = (const float*)d_in[base + 16];
    const float* fc1b = (const float*)d_in[base + 17];
    const float* fc2w = (const float*)d_in[base + 18];
    const float* fc2b = (const float*)d_in[base + 19];
    // per dir: wi, wh, bi, bh ; fwd then bwd

    float* u1; cudaGetSymbolAddress((void**)&u1, g_u1);
    float* u2; cudaGetSymbolAddress((void**)&u2, g_u2);

    // 1. weight conversion (Wih hi/lo, Whh hi/lo frag layout, bias)
    setup_w_kernel<<<1, 256>>>(
        r2[0], r2[4], r1[0], r1[4],          // Wih: tl f/b, tx f/b
        r2[1], r2[5], r1[1], r1[5],          // Whh
        r2[2], r2[3], r2[6], r2[7],          // tl biases: bif,bhf,bib,bhb
        r1[2], r1[3], r1[6], r1[7]);         // tx biases

    // 2. persistent tensor-core input GEMM (+bias)
    gemm_u_kernel<<<GEMM_GRID, 128>>>(timeline, u2, text, u1);

    // 3. tensor-core recurrence (no smem, no syncs)
    rec_tc_kernel<<<REC_GRID, 128>>>();

    seg_kernel<<<BATCH, 64>>>(elems);

    head_kernel<<<BATCH, 128>>>(normal, fc1w, fc1b, fc2w, fc2b, (float*)d_out);
}

// round 15
// speedup vs baseline: 1.4299x; 1.0562x over previous
#include <cuda_runtime.h>
#include <cuda_bf16.h>
#include <cuda_fp16.h>
#include <math.h>
#include <stdint.h>

// Problem constants (fixed by setup_inputs)
#define BATCH   512
#define TTEXT   64
#define EDIM    50
#define HDIM    32
#define NTL     32768
#define TTL     32
#define DNORM   49
#define FC_IN   305   // 64 + 49 + 64 + 64 + 64
#define GEMM_ROWS 64  // rows per GEMM tile
#define TL_TILES  16384   // NTL*TTL/GEMM_ROWS
#define TX_TILES  512     // BATCH*TTEXT/GEMM_ROWS
#define TPC       16      // tiles per persistent CTA
#define GEMM_GRID ((TL_TILES + TX_TILES) / TPC)   // 1056
#define REC_TL_CTAS 512
#define REC_TX_CTAS 8
#define REC_GRID (2 * REC_TL_CTAS + 2 * REC_TX_CTAS)   // 1040

typedef unsigned long long u64t;

// -------- device scratch (static; no runtime allocation) --------
__device__ float g_hn[BATCH * 64];            // text biRNN final hidden [B, 2H]
__device__ float g_h2[NTL * 64];              // timeline biRNN final hidden [N, 2H]
__device__ float g_mean[BATCH * 64];
__device__ float g_min[BATCH * 64];
__device__ float g_max[BATCH * 64];
__device__ __half g_u2[(size_t)NTL * TTL * 64];  // u = x@Wih^T + bias (fp16, 134 MB)
__device__ __half g_u1[BATCH * TTEXT * 64];      // u for text
__device__ __nv_bfloat16 g_wh[2][64][72];        // Wih bf16-hi  [model][n][k]
__device__ __nv_bfloat16 g_wl[2][64][72];        // Wih bf16-lo
__device__ __half g_whh_h[2][2][HDIM * HDIM];    // Whh fp16 hi [model][dir][n*32+k]
__device__ __half g_whh_l[2][2][HDIM * HDIM];    // Whh fp16 lo (residual)
__device__ float g_bias[2][64];                  // bi+bh  [model][dir*32+unit]

// tanh(x) = 1 - 2/(e^{2x}+1) via MUFU ex2/rcp (rel err ~1e-6)
__device__ __forceinline__ float fast_tanh(float x) {
    float e, r;
    asm("ex2.approx.f32 %0,%1;" : "=f"(e) : "f"(x * 2.8853900817779268f));
    asm("rcp.approx.f32 %0,%1;" : "=f"(r) : "f"(e + 1.0f));
    return fmaf(-2.0f, r, 1.0f);
}
__device__ __forceinline__ float fast_sigmoid(float x) {
    float e, r;
    asm("ex2.approx.f32 %0,%1;" : "=f"(e) : "f"(-x * 1.4426950408889634f));
    asm("rcp.approx.f32 %0,%1;" : "=f"(r) : "f"(e + 1.0f));
    return r;
}

// ---------------- TMA 1D bulk + mbarrier helpers ----------------
__device__ __forceinline__ uint32_t smem_u32(const void* p) {
    return (uint32_t)__cvta_generic_to_shared(p);
}
__device__ __forceinline__ void mbar_init(uint32_t mb, uint32_t cnt) {
    asm volatile("mbarrier.init.shared.b64 [%0], %1;" :: "r"(mb), "r"(cnt) : "memory");
}
__device__ __forceinline__ void mbar_expect_tx(uint32_t mb, uint32_t bytes) {
    asm volatile("mbarrier.arrive.expect_tx.shared.b64 _, [%0], %1;"
                 :: "r"(mb), "r"(bytes) : "memory");
}
__device__ __forceinline__ void mbar_wait(uint32_t mb, uint32_t parity) {
    asm volatile(
        "{\n\t.reg .pred P;\n\t"
        "W%=:\n\t"
        "mbarrier.try_wait.parity.acquire.cta.shared::cta.b64 P, [%0], %1, 0x989680;\n\t"
        "@!P bra W%=;\n\t}"
        :: "r"(mb), "r"(parity) : "memory");
}
__device__ __forceinline__ void tma_bulk_g2s(uint32_t dst, const void* src,
                                             uint32_t bytes, uint32_t mb) {
    asm volatile(
        "cp.async.bulk.shared::cta.global.mbarrier::complete_tx::bytes [%0], [%1], %2, [%3];"
        :: "r"(dst), "l"(src), "r"(bytes), "r"(mb) : "memory");
}
__device__ __forceinline__ void tma_bulk_s2g_commit(void* dst, uint32_t src, uint32_t bytes) {
    asm volatile("cp.async.bulk.global.shared::cta.bulk_group [%0], [%1], %2;"
                 :: "l"(dst), "r"(src), "r"(bytes) : "memory");
    asm volatile("cp.async.bulk.commit_group;" ::: "memory");
}
__device__ __forceinline__ void tma_bulk_store_wait0() {
    asm volatile("cp.async.bulk.wait_group 0;" ::: "memory");
}

// mma.sync m16n8k16 row.col f32.bf16.bf16.f32, D += A*B
#define MMA_BF16(C, A, B0, B1) \
    asm volatile("mma.sync.aligned.m16n8k16.row.col.f32.bf16.bf16.f32 " \
        "{%0,%1,%2,%3}, {%4,%5,%6,%7}, {%8,%9}, {%0,%1,%2,%3};" \
        : "+f"((C)[0]), "+f"((C)[1]), "+f"((C)[2]), "+f"((C)[3]) \
        : "r"((A)[0]), "r"((A)[1]), "r"((A)[2]), "r"((A)[3]), "r"(B0), "r"(B1))

// mma.sync m16n8k16 row.col f32.f16.f16.f32, D += A*B
#define MMA_F16(C, A, B0, B1) \
    asm volatile("mma.sync.aligned.m16n8k16.row.col.f32.f16.f16.f32 " \
        "{%0,%1,%2,%3}, {%4,%5,%6,%7}, {%8,%9}, {%0,%1,%2,%3};" \
        : "+f"((C)[0]), "+f"((C)[1]), "+f"((C)[2]), "+f"((C)[3]) \
        : "r"((A)[0]), "r"((A)[1]), "r"((A)[2]), "r"((A)[3]), "r"(B0), "r"(B1))

// fp32 pair -> bf16x2 hi + lo residual (in registers)
__device__ __forceinline__ void split_pair(float x, float y, uint32_t& hi, uint32_t& lo) {
    __nv_bfloat162 h2 = __floats2bfloat162_rn(x, y);
    float2 hb = __bfloat1622float2(h2);
    __nv_bfloat162 l2 = __floats2bfloat162_rn(x - hb.x, y - hb.y);
    hi = *(uint32_t*)&h2;
    lo = *(uint32_t*)&l2;
}
// fp32 pair -> fp16x2 (single)
__device__ __forceinline__ uint32_t pack_h2(float x, float y) {
    __half2 h = __float22half2_rn(make_float2(x, y));
    return *(uint32_t*)&h;
}

// ============================================================================
// Setup: Wih -> bf16 hi/lo; Whh -> fp16 hi/lo [model][dir][n*32+k]; bias.
// ============================================================================
__global__ void setup_w_kernel(
    const float* __restrict__ l_Wif, const float* __restrict__ l_Wib,
    const float* __restrict__ t_Wif, const float* __restrict__ t_Wib,
    const float* __restrict__ l_Whf, const float* __restrict__ l_Whb,
    const float* __restrict__ t_Whf, const float* __restrict__ t_Whb,
    const float* __restrict__ l_bif, const float* __restrict__ l_bhf,
    const float* __restrict__ l_bib, const float* __restrict__ l_bhb,
    const float* __restrict__ t_bif, const float* __restrict__ t_bhf,
    const float* __restrict__ t_bib, const float* __restrict__ t_bhb)
{
    const int tid = threadIdx.x;
    for (int idx = tid; idx < 2 * 64 * 72; idx += 256) {
        int m = idx / (64 * 72);
        int rem = idx % (64 * 72);
        int n = rem / 72, k = rem % 72;
        int d = n >> 5, unit = n & 31;
        const float* W = (m == 0) ? (d ? l_Wib : l_Wif) : (d ? t_Wib : t_Wif);
        float v = (k < EDIM) ? W[unit * EDIM + k] : 0.f;
        __nv_bfloat16 h = __float2bfloat16_rn(v);
        g_wh[m][n][k] = h;
        g_wl[m][n][k] = __float2bfloat16_rn(v - __bfloat162float(h));
    }
    for (int idx = tid; idx < 2 * 2 * HDIM * HDIM; idx += 256) {
        int m = idx >> 11;
        int rem = idx & 2047;
        int d = rem >> 10;
        int nk = rem & 1023;
        const float* W = (m == 0) ? (d ? l_Whb : l_Whf) : (d ? t_Whb : t_Whf);
        float v = W[nk];
        __half h = __float2half_rn(v);
        g_whh_h[m][d][nk] = h;
        g_whh_l[m][d][nk] = __float2half_rn(v - __half2float(h));
    }
    for (int idx = tid; idx < 128; idx += 256) {
        int m = idx >> 6, c = idx & 63, d = (c >> 5) & 1, i = c & 31;
        const float* bi = (m == 0) ? (d ? l_bib : l_bif) : (d ? t_bib : t_bif);
        const float* bh = (m == 0) ? (d ? l_bhb : l_bhf) : (d ? t_bhb : t_bhf);
        g_bias[m][c] = bi[i] + bh[i];
    }
}

// ============================================================================
// Persistent tensor-core GEMM: U = fp16(X @ Wih^T + bias)  (bf16-split mma).
// TPC tiles per CTA, double-buffered TMA bulk in, fp16 tile bulk out (8 KB).
// ============================================================================
__global__ void __launch_bounds__(128) gemm_u_kernel(
    const float* __restrict__ Xl, __half* __restrict__ Ul,
    const float* __restrict__ Xt, __half* __restrict__ Ut)
{
    __shared__ __align__(16) float  xa[2][GEMM_ROWS * EDIM];   // 2 x 12800 B
    __shared__ __align__(16) __half uo[GEMM_ROWS * 64];        // 8192 B
    __shared__ __align__(8)  u64t mbar[2];

    const int tid = threadIdx.x, w = tid >> 5, lane = tid & 31;
    const int g = lane >> 2, t = lane & 3;
    const int m0 = w * 16;
    const int tile0 = blockIdx.x * TPC;

    const uint32_t mb0 = smem_u32(&mbar[0]);
    const uint32_t mb1 = smem_u32(&mbar[1]);
    if (tid == 0) { mbar_init(mb0, 1); mbar_init(mb1, 1); }
    __syncthreads();

    if (tid == 0) {
#pragma unroll
        for (int p = 0; p < 2; ++p) {
            const int tt = tile0 + p;
            const float* X = (tt < TL_TILES)
                ? Xl + (size_t)tt * GEMM_ROWS * EDIM
                : Xt + (size_t)(tt - TL_TILES) * GEMM_ROWS * EDIM;
            const uint32_t mb = p ? mb1 : mb0;
            mbar_expect_tx(mb, GEMM_ROWS * EDIM * 4);
            tma_bulk_g2s(smem_u32(&xa[p][0]), X, GEMM_ROWS * EDIM * 4, mb);
        }
    }

    for (int i = 0; i < TPC; ++i) {
        const int cur = i & 1;
        const int tt  = tile0 + i;
        const int mdl = (tt < TL_TILES) ? 0 : 1;
        __half* U = (tt < TL_TILES)
            ? Ul + (size_t)tt * GEMM_ROWS * 64
            : Ut + (size_t)(tt - TL_TILES) * GEMM_ROWS * 64;

        mbar_wait(cur ? mb1 : mb0, (uint32_t)((i >> 1) & 1));

        uint32_t Ah[4][4], Al[4][4];
        const float* xb = &xa[cur][0];
#pragma unroll
        for (int kt = 0; kt < 4; ++kt) {
            const int ko = kt * 16 + t * 2;
#pragma unroll
            for (int half = 0; half < 2; ++half) {
                const int p = ko + half * 8;
                const bool valid = (p < EDIM);
#pragma unroll
                for (int rr = 0; rr < 2; ++rr) {
                    const int row = m0 + g + rr * 8;
                    float2 v = valid ? *(const float2*)(xb + row * EDIM + p)
                                     : make_float2(0.f, 0.f);
                    split_pair(v.x, v.y, Ah[kt][rr + half * 2], Al[kt][rr + half * 2]);
                }
            }
        }
        __syncthreads();

        if (tid == 0 && i + 2 < TPC) {
            const int tn = tile0 + i + 2;
            const float* X = (tn < TL_TILES)
                ? Xl + (size_t)tn * GEMM_ROWS * EDIM
                : Xt + (size_t)(tn - TL_TILES) * GEMM_ROWS * EDIM;
            const uint32_t mb = cur ? mb1 : mb0;
            mbar_expect_tx(mb, GEMM_ROWS * EDIM * 4);
            tma_bulk_g2s(smem_u32(&xa[cur][0]), X, GEMM_ROWS * EDIM * 4, mb);
        }

        const __nv_bfloat16* WH = &g_wh[mdl][0][0];
        const __nv_bfloat16* WL = &g_wl[mdl][0][0];

        if (tid == 0) tma_bulk_store_wait0();
        __syncthreads();

#pragma unroll
        for (int nc = 0; nc < 4; ++nc) {
            float c[2][4];
#pragma unroll
            for (int nt = 0; nt < 2; ++nt) { c[nt][0]=c[nt][1]=c[nt][2]=c[nt][3]=0.f; }
#pragma unroll
            for (int kt = 0; kt < 4; ++kt) {
                const int ko = kt * 16 + t * 2;
#pragma unroll
                for (int nt = 0; nt < 2; ++nt) {
                    const int n = nc * 16 + nt * 8 + g;
                    uint32_t bh0 = *(const uint32_t*)(WH + n * 72 + ko);
                    uint32_t bh1 = *(const uint32_t*)(WH + n * 72 + ko + 8);
                    uint32_t bl0 = *(const uint32_t*)(WL + n * 72 + ko);
                    uint32_t bl1 = *(const uint32_t*)(WL + n * 72 + ko + 8);
                    MMA_BF16(c[nt], Ah[kt], bh0, bh1);
                    MMA_BF16(c[nt], Ah[kt], bl0, bl1);
                    MMA_BF16(c[nt], Al[kt], bh0, bh1);
                }
            }
#pragma unroll
            for (int nt = 0; nt < 2; ++nt) {
                const int col = nc * 16 + nt * 8 + t * 2;
                const int row = m0 + g;
                float2 bv = *(const float2*)(&g_bias[mdl][col]);
                *(__half2*)(uo + row * 64 + col) =
                    __float22half2_rn(make_float2(c[nt][0] + bv.x, c[nt][1] + bv.y));
                *(__half2*)(uo + (row + 8) * 64 + col) =
                    __float22half2_rn(make_float2(c[nt][2] + bv.x, c[nt][3] + bv.y));
            }
        }
        __syncthreads();

        if (tid == 0) {
            asm volatile("fence.proxy.async;" ::: "memory");
            tma_bulk_s2g_commit(U, smem_u32(uo), GEMM_ROWS * 64 * 2);
        }
    }
    if (tid == 0) tma_bulk_store_wait0();
}

// ============================================================================
// Tensor-core recurrence: H_t = tanh(U_t + H_{t-1} @ Whh^T), fp16 chain.
// CTA = 64 same-direction sequences; warp = 16 (m-tile). M=64,N=32,K=32.
// A (= h) in fp16 single (error 5e-4, matches fp16 u); Whh fp16 hi+lo B-frags
// -> 16 MMA/step (was 24). u loaded as half2 (LDG.32). No smem, no syncs.
// blocks: [0,512) tl fwd | [512,1024) tl bwd | 16 text CTAs after.
// ============================================================================
__global__ void __launch_bounds__(128) rec_tc_kernel()
{
    const int tid = threadIdx.x, w = tid >> 5, lane = tid & 31;
    const int g = lane >> 2, t4 = lane & 3;
    const int blk = blockIdx.x;

    int mdl, dir, T, seq0;
    const __half* U;
    float* Hd;
    if (blk < 2 * REC_TL_CTAS) {
        mdl = 0; T = TTL; U = g_u2; Hd = g_h2;
        dir = blk >> 9;
        seq0 = (blk & 511) * 64;
    } else {
        mdl = 1; T = TTEXT; U = g_u1; Hd = g_hn;
        const int b = blk - 2 * REC_TL_CTAS;
        dir = b >> 3;
        seq0 = (b & 7) * 64;
    }

    // Whh B-fragments (fp16 hi/lo) -> registers. [kt][nt][reg]
    uint32_t Bh[2][4][2], Bl[2][4][2];
    {
        const __half* WH = &g_whh_h[mdl][dir][0];
        const __half* WL = &g_whh_l[mdl][dir][0];
#pragma unroll
        for (int kt = 0; kt < 2; ++kt) {
            const int ko = kt * 16 + t4 * 2;
#pragma unroll
            for (int nt = 0; nt < 4; ++nt) {
                const int n = nt * 8 + g;
                Bh[kt][nt][0] = *(const uint32_t*)(WH + n * HDIM + ko);
                Bh[kt][nt][1] = *(const uint32_t*)(WH + n * HDIM + ko + 8);
                Bl[kt][nt][0] = *(const uint32_t*)(WL + n * HDIM + ko);
                Bl[kt][nt][1] = *(const uint32_t*)(WL + n * HDIM + ko + 8);
            }
        }
    }

    const int row = w * 16 + g;
    const int off0 = dir * 32 + t4 * 2;
    const int tt0  = dir ? (T - 1) : 0;
    const int sgnf = dir ? -64 : 64;
    const __half* p = U + ((size_t)(seq0 + row) * T + tt0) * 64 + off0;
    const size_t rstr = (size_t)8 * T * 64;

    // c[nt][j]: D-frag layout (j0,j1 row g; j2,j3 row g+8)
    float c[4][4];
#pragma unroll
    for (int nt = 0; nt < 4; ++nt) {
        float2 v0 = __half22float2(*(const __half2*)(p + nt * 8));
        float2 v1 = __half22float2(*(const __half2*)(p + rstr + nt * 8));
        c[nt][0] = v0.x; c[nt][1] = v0.y; c[nt][2] = v1.x; c[nt][3] = v1.y;
    }

    uint32_t Ah[2][4];
    for (int t = 0; t < T; ++t) {
        // prefetch u_{t+1}
        float un[4][4];
        const bool more = (t + 1 < T);
        if (more) {
            const __half* pn = p + sgnf;
#pragma unroll
            for (int nt = 0; nt < 4; ++nt) {
                float2 v0 = __half22float2(*(const __half2*)(pn + nt * 8));
                float2 v1 = __half22float2(*(const __half2*)(pn + rstr + nt * 8));
                un[nt][0] = v0.x; un[nt][1] = v0.y; un[nt][2] = v1.x; un[nt][3] = v1.y;
            }
        }

        // C += H_{t-1} @ Whh^T (skip at t=0)
        if (t > 0) {
#pragma unroll
            for (int kt = 0; kt < 2; ++kt) {
#pragma unroll
                for (int nt = 0; nt < 4; ++nt) {
                    MMA_F16(c[nt], Ah[kt], Bh[kt][nt][0], Bh[kt][nt][1]);
                    MMA_F16(c[nt], Ah[kt], Bl[kt][nt][0], Bl[kt][nt][1]);
                }
            }
        }

        // tanh elementwise
#pragma unroll
        for (int nt = 0; nt < 4; ++nt) {
#pragma unroll
            for (int j = 0; j < 4; ++j) c[nt][j] = fast_tanh(c[nt][j]);
        }

        if (!more) break;

        // next A (fp16) from D frags: k-tile kt <- n-tiles 2kt, 2kt+1
#pragma unroll
        for (int kt = 0; kt < 2; ++kt) {
            const int na = 2 * kt, nb = 2 * kt + 1;
            Ah[kt][0] = pack_h2(c[na][0], c[na][1]);
            Ah[kt][1] = pack_h2(c[na][2], c[na][3]);
            Ah[kt][2] = pack_h2(c[nb][0], c[nb][1]);
            Ah[kt][3] = pack_h2(c[nb][2], c[nb][3]);
        }

        // shift u
#pragma unroll
        for (int nt = 0; nt < 4; ++nt)
#pragma unroll
            for (int j = 0; j < 4; ++j) c[nt][j] = un[nt][j];
        p += sgnf;
    }

    float* hb = Hd + (size_t)(seq0 + row) * 64 + off0;
#pragma unroll
    for (int nt = 0; nt < 4; ++nt) {
        *(float2*)(hb + nt * 8)          = make_float2(c[nt][0], c[nt][1]);
        *(float2*)(hb + 8 * 64 + nt * 8) = make_float2(c[nt][2], c[nt][3]);
    }
}

// ============================================================================
// Ragged segment mean/min/max over g_h2. One block (64 threads) per batch row.
// ============================================================================
__global__ void seg_kernel(const int* __restrict__ elems)
{
    const int b   = blockIdx.x;
    const int tid = threadIdx.x;
    __shared__ int sred[64];

    int partial = 0;
    for (int i = tid; i < b; i += 64) partial += elems[i];
    sred[tid] = partial;
    __syncthreads();
    for (int s = 32; s; s >>= 1) {
        if (tid < s) sred[tid] += sred[tid + s];
        __syncthreads();
    }
    const int off = sred[0];
    const int cnt = elems[b];

    float s = 0.f, mn = 3.402823466e38f, mx = -3.402823466e38f;
    const float* base = g_h2 + (size_t)off * 64 + tid;
    int r = 0;
    for (; r + 4 <= cnt; r += 4) {
        float v0 = base[(size_t)(r + 0) * 64];
        float v1 = base[(size_t)(r + 1) * 64];
        float v2 = base[(size_t)(r + 2) * 64];
        float v3 = base[(size_t)(r + 3) * 64];
        s += (v0 + v1) + (v2 + v3);
        mn = fminf(mn, fminf(fminf(v0, v1), fminf(v2, v3)));
        mx = fmaxf(mx, fmaxf(fmaxf(v0, v1), fmaxf(v2, v3)));
    }
    for (; r < cnt; ++r) {
        float v = base[(size_t)r * 64];
        s += v; mn = fminf(mn, v); mx = fmaxf(mx, v);
    }
    g_mean[b * 64 + tid] = s / (float)cnt;
    g_min[b * 64 + tid]  = mn;
    g_max[b * 64 + tid]  = mx;
}

// ============================================================================
// Head: concat(305) -> fc1 tanh -> fc2 sigmoid. 128 threads per batch row.
// ============================================================================
__global__ void __launch_bounds__(128) head_kernel(
    const float* __restrict__ normal,
    const float* __restrict__ fc1w, const float* __restrict__ fc1b,
    const float* __restrict__ fc2w, const float* __restrict__ fc2b,
    float* __restrict__ out)
{
    const int b    = blockIdx.x;
    const int tid  = threadIdx.x;
    const int wq   = tid >> 5;
    const int lane = tid & 31;
    __shared__ float xr[FC_IN + 3];
    __shared__ float part[4][32];

    if (tid < 64) {
        xr[tid]       = g_hn[b * 64 + tid];
        xr[113 + tid] = g_mean[b * 64 + tid];
        xr[177 + tid] = g_min[b * 64 + tid];
        xr[241 + tid] = g_max[b * 64 + tid];
    }
    for (int i = tid; i < DNORM; i += 128) xr[64 + i] = normal[b * DNORM + i];
    __syncthreads();

    const int k0 = wq * 76;
    const int k1 = (wq == 3) ? FC_IN : k0 + 76;
    const float* wrow = fc1w + lane * FC_IN;
    float a0 = 0.f, a1 = 0.f, a2 = 0.f, a3 = 0.f;
    int k = k0;
    for (; k + 4 <= k1; k += 4) {
        a0 += xr[k]     * wrow[k];
        a1 += xr[k + 1] * wrow[k + 1];
        a2 += xr[k + 2] * wrow[k + 2];
        a3 += xr[k + 3] * wrow[k + 3];
    }
    for (; k < k1; ++k) a0 += xr[k] * wrow[k];
    part[wq][lane] = (a0 + a1) + (a2 + a3);
    __syncthreads();

    if (wq == 0) {
        float acc = fc1b[lane] + part[0][lane] + part[1][lane] + part[2][lane] + part[3][lane];
        float pv = fast_tanh(acc) * fc2w[lane];
#pragma unroll
        for (int o = 16; o; o >>= 1) pv += __shfl_xor_sync(0xffffffffu, pv, o);
        if (lane == 0) out[b] = fast_sigmoid(pv + fc2b[0]);
    }
}

// ============================================================================
// kernel_launch
// ============================================================================
extern "C" void kernel_launch(void* const* d_in, const int* in_sizes, int n_in,
                              void* d_out, int out_size)
{
    const float* normal   = (const float*)d_in[0];
    const float* text     = (const float*)d_in[1];
    const float* timeline = (const float*)d_in[2];

    const int* elems;
    int base;
    if (in_sizes[3] == BATCH) { elems = (const int*)d_in[3]; base = 4; }
    else                      { elems = (const int*)d_in[n_in - 1]; base = 3; }

    const float* r1[8];
    const float* r2[8];
    for (int i = 0; i < 8; ++i) r1[i] = (const float*)d_in[base + i];
    for (int i = 0; i < 8; ++i) r2[i] = (const float*)d_in[base + 8 + i];
    const float* fc1w = (const float*)d_in[base + 16];
    const float* fc1b = (const float*)d_in[base + 17];
    const float* fc2w = (const float*)d_in[base + 18];
    const float* fc2b = (const float*)d_in[base + 19];
    // per dir: wi, wh, bi, bh ; fwd then bwd

    __half* u1; cudaGetSymbolAddress((void**)&u1, g_u1);
    __half* u2; cudaGetSymbolAddress((void**)&u2, g_u2);

    // 1. weight conversion
    setup_w_kernel<<<1, 256>>>(
        r2[0], r2[4], r1[0], r1[4],
        r2[1], r2[5], r1[1], r1[5],
        r2[2], r2[3], r2[6], r2[7],
        r1[2], r1[3], r1[6], r1[7]);

    // 2. persistent tensor-core input GEMM -> fp16 u
    gemm_u_kernel<<<GEMM_GRID, 128>>>(timeline, u2, text, u1);

    // 3. tensor-core recurrence (fp16 chain)
    rec_tc_kernel<<<REC_GRID, 128>>>();

    seg_kernel<<<BATCH, 64>>>(elems);

    head_kernel<<<BATCH, 128>>>(normal, fc1w, fc1b, fc2w, fc2b, (float*)d_out);
}

// round 16
// speedup vs baseline: 1.5058x; 1.0531x over previous
#include <cuda_runtime.h>
#include <cuda_bf16.h>
#include <cuda_fp16.h>
#include <math.h>
#include <stdint.h>

// Problem constants (fixed by setup_inputs)
#define BATCH   512
#define TTEXT   64
#define EDIM    50
#define HDIM    32
#define NTL     32768
#define TTL     32
#define DNORM   49
#define FC_IN   305   // 64 + 49 + 64 + 64 + 64
#define GEMM_ROWS 64  // rows per GEMM tile
#define TL_TILES  16384   // NTL*TTL/GEMM_ROWS
#define TX_TILES  512     // BATCH*TTEXT/GEMM_ROWS
#define TPC       33      // tiles per persistent CTA
#define GEMM_GRID ((TL_TILES + TX_TILES) / TPC)   // 512 exactly
#define REC_TL_CTAS 512
#define REC_TX_CTAS 8
#define REC_GRID (2 * REC_TL_CTAS + 2 * REC_TX_CTAS)   // 1040

typedef unsigned long long u64t;

// -------- device scratch (static; no runtime allocation) --------
__device__ float g_hn[BATCH * 64];            // text biRNN final hidden [B, 2H]
__device__ float g_h2[NTL * 64];              // timeline biRNN final hidden [N, 2H]
__device__ __half g_u2[(size_t)NTL * TTL * 64];  // u = x@Wih^T + bias (fp16)
__device__ __half g_u1[BATCH * TTEXT * 64];      // u for text
__device__ __nv_bfloat16 g_wh[2][64][72];        // Wih bf16-hi  [model][n][k]
__device__ __nv_bfloat16 g_wl[2][64][72];        // Wih bf16-lo
__device__ __half g_whh_h[2][2][HDIM * HDIM];    // Whh fp16 hi [model][dir][n*32+k]
__device__ __half g_whh_l[2][2][HDIM * HDIM];    // Whh fp16 lo (residual)
__device__ float g_bias[2][64];                  // bi+bh  [model][dir*32+unit]

// tanh(x) = 1 - 2/(e^{2x}+1) via MUFU ex2/rcp (rel err ~1e-6)
__device__ __forceinline__ float fast_tanh(float x) {
    float e, r;
    asm("ex2.approx.f32 %0,%1;" : "=f"(e) : "f"(x * 2.8853900817779268f));
    asm("rcp.approx.f32 %0,%1;" : "=f"(r) : "f"(e + 1.0f));
    return fmaf(-2.0f, r, 1.0f);
}
__device__ __forceinline__ float fast_sigmoid(float x) {
    float e, r;
    asm("ex2.approx.f32 %0,%1;" : "=f"(e) : "f"(-x * 1.4426950408889634f));
    asm("rcp.approx.f32 %0,%1;" : "=f"(r) : "f"(e + 1.0f));
    return r;
}

// ---------------- TMA 1D bulk + mbarrier helpers ----------------
__device__ __forceinline__ uint32_t smem_u32(const void* p) {
    return (uint32_t)__cvta_generic_to_shared(p);
}
__device__ __forceinline__ void mbar_init(uint32_t mb, uint32_t cnt) {
    asm volatile("mbarrier.init.shared.b64 [%0], %1;" :: "r"(mb), "r"(cnt) : "memory");
}
__device__ __forceinline__ void mbar_expect_tx(uint32_t mb, uint32_t bytes) {
    asm volatile("mbarrier.arrive.expect_tx.shared.b64 _, [%0], %1;"
                 :: "r"(mb), "r"(bytes) : "memory");
}
__device__ __forceinline__ void mbar_wait(uint32_t mb, uint32_t parity) {
    asm volatile(
        "{\n\t.reg .pred P;\n\t"
        "W%=:\n\t"
        "mbarrier.try_wait.parity.acquire.cta.shared::cta.b64 P, [%0], %1, 0x989680;\n\t"
        "@!P bra W%=;\n\t}"
        :: "r"(mb), "r"(parity) : "memory");
}
__device__ __forceinline__ void tma_bulk_g2s(uint32_t dst, const void* src,
                                             uint32_t bytes, uint32_t mb) {
    asm volatile(
        "cp.async.bulk.shared::cta.global.mbarrier::complete_tx::bytes [%0], [%1], %2, [%3];"
        :: "r"(dst), "l"(src), "r"(bytes), "r"(mb) : "memory");
}
__device__ __forceinline__ void tma_bulk_s2g_commit(void* dst, uint32_t src, uint32_t bytes) {
    asm volatile("cp.async.bulk.global.shared::cta.bulk_group [%0], [%1], %2;"
                 :: "l"(dst), "r"(src), "r"(bytes) : "memory");
    asm volatile("cp.async.bulk.commit_group;" ::: "memory");
}
__device__ __forceinline__ void tma_bulk_store_wait1() {
    asm volatile("cp.async.bulk.wait_group 1;" ::: "memory");
}
__device__ __forceinline__ void tma_bulk_store_wait0() {
    asm volatile("cp.async.bulk.wait_group 0;" ::: "memory");
}

// mma.sync m16n8k16 row.col f32.bf16.bf16.f32, D += A*B
#define MMA_BF16(C, A, B0, B1) \
    asm volatile("mma.sync.aligned.m16n8k16.row.col.f32.bf16.bf16.f32 " \
        "{%0,%1,%2,%3}, {%4,%5,%6,%7}, {%8,%9}, {%0,%1,%2,%3};" \
        : "+f"((C)[0]), "+f"((C)[1]), "+f"((C)[2]), "+f"((C)[3]) \
        : "r"((A)[0]), "r"((A)[1]), "r"((A)[2]), "r"((A)[3]), "r"(B0), "r"(B1))

// mma.sync m16n8k16 row.col f32.f16.f16.f32, D += A*B
#define MMA_F16(C, A, B0, B1) \
    asm volatile("mma.sync.aligned.m16n8k16.row.col.f32.f16.f16.f32 " \
        "{%0,%1,%2,%3}, {%4,%5,%6,%7}, {%8,%9}, {%0,%1,%2,%3};" \
        : "+f"((C)[0]), "+f"((C)[1]), "+f"((C)[2]), "+f"((C)[3]) \
        : "r"((A)[0]), "r"((A)[1]), "r"((A)[2]), "r"((A)[3]), "r"(B0), "r"(B1))

// fp32 pair -> bf16x2 hi + lo residual (in registers)
__device__ __forceinline__ void split_pair(float x, float y, uint32_t& hi, uint32_t& lo) {
    __nv_bfloat162 h2 = __floats2bfloat162_rn(x, y);
    float2 hb = __bfloat1622float2(h2);
    __nv_bfloat162 l2 = __floats2bfloat162_rn(x - hb.x, y - hb.y);
    hi = *(uint32_t*)&h2;
    lo = *(uint32_t*)&l2;
}
// fp32 pair -> fp16x2 (single)
__device__ __forceinline__ uint32_t pack_h2(float x, float y) {
    __half2 h = __float22half2_rn(make_float2(x, y));
    return *(uint32_t*)&h;
}

// ============================================================================
// Setup: Wih -> bf16 hi/lo; Whh -> fp16 hi/lo; bias. 64 small blocks.
// ============================================================================
__global__ void setup_w_kernel(
    const float* __restrict__ l_Wif, const float* __restrict__ l_Wib,
    const float* __restrict__ t_Wif, const float* __restrict__ t_Wib,
    const float* __restrict__ l_Whf, const float* __restrict__ l_Whb,
    const float* __restrict__ t_Whf, const float* __restrict__ t_Whb,
    const float* __restrict__ l_bif, const float* __restrict__ l_bhf,
    const float* __restrict__ l_bib, const float* __restrict__ l_bhb,
    const float* __restrict__ t_bif, const float* __restrict__ t_bhf,
    const float* __restrict__ t_bib, const float* __restrict__ t_bhb)
{
    const int gtid = blockIdx.x * blockDim.x + threadIdx.x;
    const int gstr = gridDim.x * blockDim.x;
    for (int idx = gtid; idx < 2 * 64 * 72; idx += gstr) {
        int m = idx / (64 * 72);
        int rem = idx % (64 * 72);
        int n = rem / 72, k = rem % 72;
        int d = n >> 5, unit = n & 31;
        const float* W = (m == 0) ? (d ? l_Wib : l_Wif) : (d ? t_Wib : t_Wif);
        float v = (k < EDIM) ? W[unit * EDIM + k] : 0.f;
        __nv_bfloat16 h = __float2bfloat16_rn(v);
        g_wh[m][n][k] = h;
        g_wl[m][n][k] = __float2bfloat16_rn(v - __bfloat162float(h));
    }
    for (int idx = gtid; idx < 2 * 2 * HDIM * HDIM; idx += gstr) {
        int m = idx >> 11;
        int rem = idx & 2047;
        int d = rem >> 10;
        int nk = rem & 1023;
        const float* W = (m == 0) ? (d ? l_Whb : l_Whf) : (d ? t_Whb : t_Whf);
        float v = W[nk];
        __half h = __float2half_rn(v);
        g_whh_h[m][d][nk] = h;
        g_whh_l[m][d][nk] = __float2half_rn(v - __half2float(h));
    }
    for (int idx = gtid; idx < 128; idx += gstr) {
        int m = idx >> 6, c = idx & 63, d = (c >> 5) & 1, i = c & 31;
        const float* bi = (m == 0) ? (d ? l_bib : l_bif) : (d ? t_bib : t_bif);
        const float* bh = (m == 0) ? (d ? l_bhb : l_bhf) : (d ? t_bhb : t_bhf);
        g_bias[m][c] = bi[i] + bh[i];
    }
}

// ============================================================================
// Persistent tensor-core GEMM: U = fp16(X @ Wih^T + bias)  (bf16-split mma).
// TPC=33 tiles per CTA -> exactly 512 CTAs (single balanced wave).
// Double-buffered TMA bulk in; DOUBLE-BUFFERED uo out (wait_group 1: only the
// same-buffer store from tile i-2 must drain; i-1's store overlaps our mma).
// ============================================================================
__global__ void __launch_bounds__(128) gemm_u_kernel(
    const float* __restrict__ Xl, __half* __restrict__ Ul,
    const float* __restrict__ Xt, __half* __restrict__ Ut)
{
    __shared__ __align__(16) float  xa[2][GEMM_ROWS * EDIM];   // 2 x 12800 B
    __shared__ __align__(16) __half uo[2][GEMM_ROWS * 64];     // 2 x 8192 B
    __shared__ __align__(8)  u64t mbar[2];

    const int tid = threadIdx.x, w = tid >> 5, lane = tid & 31;
    const int g = lane >> 2, t = lane & 3;
    const int m0 = w * 16;
    const int tile0 = blockIdx.x * TPC;

    const uint32_t mb0 = smem_u32(&mbar[0]);
    const uint32_t mb1 = smem_u32(&mbar[1]);
    if (tid == 0) { mbar_init(mb0, 1); mbar_init(mb1, 1); }
    __syncthreads();

    if (tid == 0) {
#pragma unroll
        for (int p = 0; p < 2; ++p) {
            const int tt = tile0 + p;
            const float* X = (tt < TL_TILES)
                ? Xl + (size_t)tt * GEMM_ROWS * EDIM
                : Xt + (size_t)(tt - TL_TILES) * GEMM_ROWS * EDIM;
            const uint32_t mb = p ? mb1 : mb0;
            mbar_expect_tx(mb, GEMM_ROWS * EDIM * 4);
            tma_bulk_g2s(smem_u32(&xa[p][0]), X, GEMM_ROWS * EDIM * 4, mb);
        }
    }

    for (int i = 0; i < TPC; ++i) {
        const int cur = i & 1;
        const int tt  = tile0 + i;
        const int mdl = (tt < TL_TILES) ? 0 : 1;
        __half* U = (tt < TL_TILES)
            ? Ul + (size_t)tt * GEMM_ROWS * 64
            : Ut + (size_t)(tt - TL_TILES) * GEMM_ROWS * 64;

        mbar_wait(cur ? mb1 : mb0, (uint32_t)((i >> 1) & 1));

        uint32_t Ah[4][4], Al[4][4];
        const float* xb = &xa[cur][0];
#pragma unroll
        for (int kt = 0; kt < 4; ++kt) {
            const int ko = kt * 16 + t * 2;
#pragma unroll
            for (int half = 0; half < 2; ++half) {
                const int p = ko + half * 8;
                const bool valid = (p < EDIM);
#pragma unroll
                for (int rr = 0; rr < 2; ++rr) {
                    const int row = m0 + g + rr * 8;
                    float2 v = valid ? *(const float2*)(xb + row * EDIM + p)
                                     : make_float2(0.f, 0.f);
                    split_pair(v.x, v.y, Ah[kt][rr + half * 2], Al[kt][rr + half * 2]);
                }
            }
        }
        __syncthreads();

        if (tid == 0 && i + 2 < TPC) {
            const int tn = tile0 + i + 2;
            const float* X = (tn < TL_TILES)
                ? Xl + (size_t)tn * GEMM_ROWS * EDIM
                : Xt + (size_t)(tn - TL_TILES) * GEMM_ROWS * EDIM;
            const uint32_t mb = cur ? mb1 : mb0;
            mbar_expect_tx(mb, GEMM_ROWS * EDIM * 4);
            tma_bulk_g2s(smem_u32(&xa[cur][0]), X, GEMM_ROWS * EDIM * 4, mb);
        }

        const __nv_bfloat16* WH = &g_wh[mdl][0][0];
        const __nv_bfloat16* WL = &g_wl[mdl][0][0];

        // only the same-buffer store (tile i-2) must be done; i-1 overlaps
        if (tid == 0) tma_bulk_store_wait1();
        __syncthreads();

        __half* uw = &uo[cur][0];
#pragma unroll
        for (int nc = 0; nc < 4; ++nc) {
            float c[2][4];
#pragma unroll
            for (int nt = 0; nt < 2; ++nt) { c[nt][0]=c[nt][1]=c[nt][2]=c[nt][3]=0.f; }
#pragma unroll
            for (int kt = 0; kt < 4; ++kt) {
                const int ko = kt * 16 + t * 2;
#pragma unroll
                for (int nt = 0; nt < 2; ++nt) {
                    const int n = nc * 16 + nt * 8 + g;
                    uint32_t bh0 = *(const uint32_t*)(WH + n * 72 + ko);
                    uint32_t bh1 = *(const uint32_t*)(WH + n * 72 + ko + 8);
                    uint32_t bl0 = *(const uint32_t*)(WL + n * 72 + ko);
                    uint32_t bl1 = *(const uint32_t*)(WL + n * 72 + ko + 8);
                    MMA_BF16(c[nt], Ah[kt], bh0, bh1);
                    MMA_BF16(c[nt], Ah[kt], bl0, bl1);
                    MMA_BF16(c[nt], Al[kt], bh0, bh1);
                }
            }
#pragma unroll
            for (int nt = 0; nt < 2; ++nt) {
                const int col = nc * 16 + nt * 8 + t * 2;
                const int row = m0 + g;
                float2 bv = *(const float2*)(&g_bias[mdl][col]);
                *(__half2*)(uw + row * 64 + col) =
                    __float22half2_rn(make_float2(c[nt][0] + bv.x, c[nt][1] + bv.y));
                *(__half2*)(uw + (row + 8) * 64 + col) =
                    __float22half2_rn(make_float2(c[nt][2] + bv.x, c[nt][3] + bv.y));
            }
        }
        __syncthreads();

        if (tid == 0) {
            asm volatile("fence.proxy.async;" ::: "memory");
            tma_bulk_s2g_commit(U, smem_u32(uw), GEMM_ROWS * 64 * 2);
        }
    }
    if (tid == 0) tma_bulk_store_wait0();
}

// ============================================================================
// Tensor-core recurrence: H_t = tanh(U_t + H_{t-1} @ Whh^T), fp16 chain.
// (unchanged from R15: D-frag->A-frag chaining, fp16 A + Whh hi/lo = 16 MMA.)
// ============================================================================
__global__ void __launch_bounds__(128) rec_tc_kernel()
{
    const int tid = threadIdx.x, w = tid >> 5, lane = tid & 31;
    const int g = lane >> 2, t4 = lane & 3;
    const int blk = blockIdx.x;

    int mdl, dir, T, seq0;
    const __half* U;
    float* Hd;
    if (blk < 2 * REC_TL_CTAS) {
        mdl = 0; T = TTL; U = g_u2; Hd = g_h2;
        dir = blk >> 9;
        seq0 = (blk & 511) * 64;
    } else {
        mdl = 1; T = TTEXT; U = g_u1; Hd = g_hn;
        const int b = blk - 2 * REC_TL_CTAS;
        dir = b >> 3;
        seq0 = (b & 7) * 64;
    }

    uint32_t Bh[2][4][2], Bl[2][4][2];
    {
        const __half* WH = &g_whh_h[mdl][dir][0];
        const __half* WL = &g_whh_l[mdl][dir][0];
#pragma unroll
        for (int kt = 0; kt < 2; ++kt) {
            const int ko = kt * 16 + t4 * 2;
#pragma unroll
            for (int nt = 0; nt < 4; ++nt) {
                const int n = nt * 8 + g;
                Bh[kt][nt][0] = *(const uint32_t*)(WH + n * HDIM + ko);
                Bh[kt][nt][1] = *(const uint32_t*)(WH + n * HDIM + ko + 8);
                Bl[kt][nt][0] = *(const uint32_t*)(WL + n * HDIM + ko);
                Bl[kt][nt][1] = *(const uint32_t*)(WL + n * HDIM + ko + 8);
            }
        }
    }

    const int row = w * 16 + g;
    const int off0 = dir * 32 + t4 * 2;
    const int tt0  = dir ? (T - 1) : 0;
    const int sgnf = dir ? -64 : 64;
    const __half* p = U + ((size_t)(seq0 + row) * T + tt0) * 64 + off0;
    const size_t rstr = (size_t)8 * T * 64;

    float c[4][4];
#pragma unroll
    for (int nt = 0; nt < 4; ++nt) {
        float2 v0 = __half22float2(*(const __half2*)(p + nt * 8));
        float2 v1 = __half22float2(*(const __half2*)(p + rstr + nt * 8));
        c[nt][0] = v0.x; c[nt][1] = v0.y; c[nt][2] = v1.x; c[nt][3] = v1.y;
    }

    uint32_t Ah[2][4];
    for (int t = 0; t < T; ++t) {
        float un[4][4];
        const bool more = (t + 1 < T);
        if (more) {
            const __half* pn = p + sgnf;
#pragma unroll
            for (int nt = 0; nt < 4; ++nt) {
                float2 v0 = __half22float2(*(const __half2*)(pn + nt * 8));
                float2 v1 = __half22float2(*(const __half2*)(pn + rstr + nt * 8));
                un[nt][0] = v0.x; un[nt][1] = v0.y; un[nt][2] = v1.x; un[nt][3] = v1.y;
            }
        }

        if (t > 0) {
#pragma unroll
            for (int kt = 0; kt < 2; ++kt) {
#pragma unroll
                for (int nt = 0; nt < 4; ++nt) {
                    MMA_F16(c[nt], Ah[kt], Bh[kt][nt][0], Bh[kt][nt][1]);
                    MMA_F16(c[nt], Ah[kt], Bl[kt][nt][0], Bl[kt][nt][1]);
                }
            }
        }

#pragma unroll
        for (int nt = 0; nt < 4; ++nt) {
#pragma unroll
            for (int j = 0; j < 4; ++j) c[nt][j] = fast_tanh(c[nt][j]);
        }

        if (!more) break;

#pragma unroll
        for (int kt = 0; kt < 2; ++kt) {
            const int na = 2 * kt, nb = 2 * kt + 1;
            Ah[kt][0] = pack_h2(c[na][0], c[na][1]);
            Ah[kt][1] = pack_h2(c[na][2], c[na][3]);
            Ah[kt][2] = pack_h2(c[nb][0], c[nb][1]);
            Ah[kt][3] = pack_h2(c[nb][2], c[nb][3]);
        }

#pragma unroll
        for (int nt = 0; nt < 4; ++nt)
#pragma unroll
            for (int j = 0; j < 4; ++j) c[nt][j] = un[nt][j];
        p += sgnf;
    }

    float* hb = Hd + (size_t)(seq0 + row) * 64 + off0;
#pragma unroll
    for (int nt = 0; nt < 4; ++nt) {
        *(float2*)(hb + nt * 8)          = make_float2(c[nt][0], c[nt][1]);
        *(float2*)(hb + 8 * 64 + nt * 8) = make_float2(c[nt][2], c[nt][3]);
    }
}

// ============================================================================
// Merged segment stats + head. One 128-thread block per batch row:
// threads 0-63 compute mean/min/max for their column straight into xr;
// threads 64-127 stage normal. Then fc1 (4-warp k-split) -> tanh -> fc2 ->
// sigmoid. Kills the g_mean/min/max DRAM round trip and one launch.
// ============================================================================
__global__ void __launch_bounds__(128) seg_head_kernel(
    const int* __restrict__ elems,
    const float* __restrict__ normal,
    const float* __restrict__ fc1w, const float* __restrict__ fc1b,
    const float* __restrict__ fc2w, const float* __restrict__ fc2b,
    float* __restrict__ out)
{
    const int b    = blockIdx.x;
    const int tid  = threadIdx.x;
    const int wq   = tid >> 5;
    const int lane = tid & 31;
    __shared__ float xr[FC_IN + 3];
    __shared__ float part[4][32];
    __shared__ int sred[128];

    // prefix sum of elems[0..b)
    int partial = 0;
    for (int i = tid; i < b; i += 128) partial += elems[i];
    sred[tid] = partial;
    __syncthreads();
    for (int s = 64; s; s >>= 1) {
        if (tid < s) sred[tid] += sred[tid + s];
        __syncthreads();
    }
    const int off = sred[0];
    const int cnt = elems[b];

    if (tid < 64) {
        // column stats over cnt rows
        float s = 0.f, mn = 3.402823466e38f, mx = -3.402823466e38f;
        const float* base = g_h2 + (size_t)off * 64 + tid;
        int r = 0;
        for (; r + 4 <= cnt; r += 4) {
            float v0 = base[(size_t)(r + 0) * 64];
            float v1 = base[(size_t)(r + 1) * 64];
            float v2 = base[(size_t)(r + 2) * 64];
            float v3 = base[(size_t)(r + 3) * 64];
            s += (v0 + v1) + (v2 + v3);
            mn = fminf(mn, fminf(fminf(v0, v1), fminf(v2, v3)));
            mx = fmaxf(mx, fmaxf(fmaxf(v0, v1), fmaxf(v2, v3)));
        }
        for (; r < cnt; ++r) {
            float v = base[(size_t)r * 64];
            s += v; mn = fminf(mn, v); mx = fmaxf(mx, v);
        }
        xr[tid]       = g_hn[b * 64 + tid];
        xr[113 + tid] = s / (float)cnt;
        xr[177 + tid] = mn;
        xr[241 + tid] = mx;
    } else {
        for (int i = tid - 64; i < DNORM; i += 64) xr[64 + i] = normal[b * DNORM + i];
    }
    __syncthreads();

    const int k0 = wq * 76;
    const int k1 = (wq == 3) ? FC_IN : k0 + 76;
    const float* wrow = fc1w + lane * FC_IN;
    float a0 = 0.f, a1 = 0.f, a2 = 0.f, a3 = 0.f;
    int k = k0;
    for (; k + 4 <= k1; k += 4) {
        a0 += xr[k]     * wrow[k];
        a1 += xr[k + 1] * wrow[k + 1];
        a2 += xr[k + 2] * wrow[k + 2];
        a3 += xr[k + 3] * wrow[k + 3];
    }
    for (; k < k1; ++k) a0 += xr[k] * wrow[k];
    part[wq][lane] = (a0 + a1) + (a2 + a3);
    __syncthreads();

    if (wq == 0) {
        float acc = fc1b[lane] + part[0][lane] + part[1][lane] + part[2][lane] + part[3][lane];
        float pv = fast_tanh(acc) * fc2w[lane];
#pragma unroll
        for (int o = 16; o; o >>= 1) pv += __shfl_xor_sync(0xffffffffu, pv, o);
        if (lane == 0) out[b] = fast_sigmoid(pv + fc2b[0]);
    }
}

// ============================================================================
// kernel_launch
// ============================================================================
extern "C" void kernel_launch(void* const* d_in, const int* in_sizes, int n_in,
                              void* d_out, int out_size)
{
    const float* normal   = (const float*)d_in[0];
    const float* text     = (const float*)d_in[1];
    const float* timeline = (const float*)d_in[2];

    const int* elems;
    int base;
    if (in_sizes[3] == BATCH) { elems = (const int*)d_in[3]; base = 4; }
    else                      { elems = (const int*)d_in[n_in - 1]; base = 3; }

    const float* r1[8];
    const float* r2[8];
    for (int i = 0; i < 8; ++i) r1[i] = (const float*)d_in[base + i];
    for (int i = 0; i < 8; ++i) r2[i] = (const float*)d_in[base + 8 + i];
    const float* fc1w = (const float*)d_in[base + 16];
    const float* fc1b = (const float*)d_in[base + 17];
    const float* fc2w = (const float*)d_in[base + 18];
    const float* fc2b = (const float*)d_in[base + 19];
    // per dir: wi, wh, bi, bh ; fwd then bwd

    __half* u1; cudaGetSymbolAddress((void**)&u1, g_u1);
    __half* u2; cudaGetSymbolAddress((void**)&u2, g_u2);

    // 1. weight conversion (spread over 64 blocks)
    setup_w_kernel<<<64, 128>>>(
        r2[0], r2[4], r1[0], r1[4],
        r2[1], r2[5], r1[1], r1[5],
        r2[2], r2[3], r2[6], r2[7],
        r1[2], r1[3], r1[6], r1[7]);

    // 2. persistent tensor-core input GEMM -> fp16 u (512 CTAs, single wave)
    gemm_u_kernel<<<GEMM_GRID, 128>>>(timeline, u2, text, u1);

    // 3. tensor-core recurrence (fp16 chain)
    rec_tc_kernel<<<REC_GRID, 128>>>();

    // 4. merged segment stats + head
    seg_head_kernel<<<BATCH, 128>>>(elems, normal, fc1w, fc1b, fc2w, fc2b,
                                    (float*)d_out);
}

// round 17
// speedup vs baseline: 1.5219x; 1.0106x over previous
#include <cuda_runtime.h>
#include <cuda_bf16.h>
#include <cuda_fp16.h>
#include <math.h>
#include <stdint.h>

// Problem constants (fixed by setup_inputs)
#define BATCH   512
#define TTEXT   64
#define EDIM    50
#define HDIM    32
#define NTL     32768
#define TTL     32
#define DNORM   49
#define FC_IN   305   // 64 + 49 + 64 + 64 + 64
#define GEMM_ROWS 64  // rows per GEMM tile
#define TL_TILES  16384   // NTL*TTL/GEMM_ROWS
#define TX_TILES  512     // BATCH*TTEXT/GEMM_ROWS
#define TPC       22      // tiles per persistent CTA
#define GEMM_GRID ((TL_TILES + TX_TILES) / TPC)   // 768 exactly
#define REC_TL_CTAS 512
#define REC_TX_CTAS 8
#define REC_GRID (2 * REC_TL_CTAS + 2 * REC_TX_CTAS)   // 1040

typedef unsigned long long u64t;

// -------- device scratch (static; no runtime allocation) --------
__device__ float g_hn[BATCH * 64];            // text biRNN final hidden [B, 2H]
__device__ float g_h2[NTL * 64];              // timeline biRNN final hidden [N, 2H]
__device__ __half g_u2[(size_t)NTL * TTL * 64];  // u = x@Wih^T + bias (fp16)
__device__ __half g_u1[BATCH * TTEXT * 64];      // u for text
__device__ __nv_bfloat16 g_wh[2][64][72];        // Wih bf16-hi  [model][n][k]
__device__ __nv_bfloat16 g_wl[2][64][72];        // Wih bf16-lo
__device__ __half g_whh_h[2][2][HDIM * HDIM];    // Whh fp16 hi [model][dir][n*32+k]
__device__ __half g_whh_l[2][2][HDIM * HDIM];    // Whh fp16 lo (residual)
__device__ float g_bias[2][64];                  // bi+bh  [model][dir*32+unit]

// tanh(x) = 1 - 2/(e^{2x}+1) via MUFU ex2/rcp (rel err ~1e-6)
__device__ __forceinline__ float fast_tanh(float x) {
    float e, r;
    asm("ex2.approx.f32 %0,%1;" : "=f"(e) : "f"(x * 2.8853900817779268f));
    asm("rcp.approx.f32 %0,%1;" : "=f"(r) : "f"(e + 1.0f));
    return fmaf(-2.0f, r, 1.0f);
}
__device__ __forceinline__ float fast_sigmoid(float x) {
    float e, r;
    asm("ex2.approx.f32 %0,%1;" : "=f"(e) : "f"(-x * 1.4426950408889634f));
    asm("rcp.approx.f32 %0,%1;" : "=f"(r) : "f"(e + 1.0f));
    return r;
}

// ---------------- TMA 1D bulk + mbarrier helpers ----------------
__device__ __forceinline__ uint32_t smem_u32(const void* p) {
    return (uint32_t)__cvta_generic_to_shared(p);
}
__device__ __forceinline__ void mbar_init(uint32_t mb, uint32_t cnt) {
    asm volatile("mbarrier.init.shared.b64 [%0], %1;" :: "r"(mb), "r"(cnt) : "memory");
}
__device__ __forceinline__ void mbar_expect_tx(uint32_t mb, uint32_t bytes) {
    asm volatile("mbarrier.arrive.expect_tx.shared.b64 _, [%0], %1;"
                 :: "r"(mb), "r"(bytes) : "memory");
}
__device__ __forceinline__ void mbar_wait(uint32_t mb, uint32_t parity) {
    asm volatile(
        "{\n\t.reg .pred P;\n\t"
        "W%=:\n\t"
        "mbarrier.try_wait.parity.acquire.cta.shared::cta.b64 P, [%0], %1, 0x989680;\n\t"
        "@!P bra W%=;\n\t}"
        :: "r"(mb), "r"(parity) : "memory");
}
__device__ __forceinline__ void tma_bulk_g2s(uint32_t dst, const void* src,
                                             uint32_t bytes, uint32_t mb) {
    asm volatile(
        "cp.async.bulk.shared::cta.global.mbarrier::complete_tx::bytes [%0], [%1], %2, [%3];"
        :: "r"(dst), "l"(src), "r"(bytes), "r"(mb) : "memory");
}
__device__ __forceinline__ void tma_bulk_s2g_commit(void* dst, uint32_t src, uint32_t bytes) {
    asm volatile("cp.async.bulk.global.shared::cta.bulk_group [%0], [%1], %2;"
                 :: "l"(dst), "r"(src), "r"(bytes) : "memory");
    asm volatile("cp.async.bulk.commit_group;" ::: "memory");
}
__device__ __forceinline__ void tma_bulk_store_wait1() {
    asm volatile("cp.async.bulk.wait_group 1;" ::: "memory");
}
__device__ __forceinline__ void tma_bulk_store_wait0() {
    asm volatile("cp.async.bulk.wait_group 0;" ::: "memory");
}

// mma.sync m16n8k16 row.col f32.bf16.bf16.f32, D += A*B
#define MMA_BF16(C, A, B0, B1) \
    asm volatile("mma.sync.aligned.m16n8k16.row.col.f32.bf16.bf16.f32 " \
        "{%0,%1,%2,%3}, {%4,%5,%6,%7}, {%8,%9}, {%0,%1,%2,%3};" \
        : "+f"((C)[0]), "+f"((C)[1]), "+f"((C)[2]), "+f"((C)[3]) \
        : "r"((A)[0]), "r"((A)[1]), "r"((A)[2]), "r"((A)[3]), "r"(B0), "r"(B1))

// mma.sync m16n8k16 row.col f32.f16.f16.f32, D += A*B
#define MMA_F16(C, A, B0, B1) \
    asm volatile("mma.sync.aligned.m16n8k16.row.col.f32.f16.f16.f32 " \
        "{%0,%1,%2,%3}, {%4,%5,%6,%7}, {%8,%9}, {%0,%1,%2,%3};" \
        : "+f"((C)[0]), "+f"((C)[1]), "+f"((C)[2]), "+f"((C)[3]) \
        : "r"((A)[0]), "r"((A)[1]), "r"((A)[2]), "r"((A)[3]), "r"(B0), "r"(B1))

// fp32 pair -> bf16x2 hi + lo residual (in registers)
__device__ __forceinline__ void split_pair(float x, float y, uint32_t& hi, uint32_t& lo) {
    __nv_bfloat162 h2 = __floats2bfloat162_rn(x, y);
    float2 hb = __bfloat1622float2(h2);
    __nv_bfloat162 l2 = __floats2bfloat162_rn(x - hb.x, y - hb.y);
    hi = *(uint32_t*)&h2;
    lo = *(uint32_t*)&l2;
}
// fp32 pair -> fp16x2 (single)
__device__ __forceinline__ uint32_t pack_h2(float x, float y) {
    __half2 h = __float22half2_rn(make_float2(x, y));
    return *(uint32_t*)&h;
}

// ============================================================================
// Setup: Wih -> bf16 hi/lo; Whh -> fp16 hi/lo; bias. 64 small blocks.
// ============================================================================
__global__ void setup_w_kernel(
    const float* __restrict__ l_Wif, const float* __restrict__ l_Wib,
    const float* __restrict__ t_Wif, const float* __restrict__ t_Wib,
    const float* __restrict__ l_Whf, const float* __restrict__ l_Whb,
    const float* __restrict__ t_Whf, const float* __restrict__ t_Whb,
    const float* __restrict__ l_bif, const float* __restrict__ l_bhf,
    const float* __restrict__ l_bib, const float* __restrict__ l_bhb,
    const float* __restrict__ t_bif, const float* __restrict__ t_bhf,
    const float* __restrict__ t_bib, const float* __restrict__ t_bhb)
{
    const int gtid = blockIdx.x * blockDim.x + threadIdx.x;
    const int gstr = gridDim.x * blockDim.x;
    for (int idx = gtid; idx < 2 * 64 * 72; idx += gstr) {
        int m = idx / (64 * 72);
        int rem = idx % (64 * 72);
        int n = rem / 72, k = rem % 72;
        int d = n >> 5, unit = n & 31;
        const float* W = (m == 0) ? (d ? l_Wib : l_Wif) : (d ? t_Wib : t_Wif);
        float v = (k < EDIM) ? W[unit * EDIM + k] : 0.f;
        __nv_bfloat16 h = __float2bfloat16_rn(v);
        g_wh[m][n][k] = h;
        g_wl[m][n][k] = __float2bfloat16_rn(v - __bfloat162float(h));
    }
    for (int idx = gtid; idx < 2 * 2 * HDIM * HDIM; idx += gstr) {
        int m = idx >> 11;
        int rem = idx & 2047;
        int d = rem >> 10;
        int nk = rem & 1023;
        const float* W = (m == 0) ? (d ? l_Whb : l_Whf) : (d ? t_Whb : t_Whf);
        float v = W[nk];
        __half h = __float2half_rn(v);
        g_whh_h[m][d][nk] = h;
        g_whh_l[m][d][nk] = __float2half_rn(v - __half2float(h));
    }
    for (int idx = gtid; idx < 128; idx += gstr) {
        int m = idx >> 6, c = idx & 63, d = (c >> 5) & 1, i = c & 31;
        const float* bi = (m == 0) ? (d ? l_bib : l_bif) : (d ? t_bib : t_bif);
        const float* bh = (m == 0) ? (d ? l_bhb : l_bhf) : (d ? t_bhb : t_bhf);
        g_bias[m][c] = bi[i] + bh[i];
    }
}

// ============================================================================
// Persistent tensor-core GEMM: U = fp16(X @ Wih^T + bias)  (bf16-split mma).
// TPC=22 -> 768 CTAs (~5.2/SM vs smem cap 5): higher DRAM MLP, near-1 wave.
// Double-buffered TMA in; double-buffered uo out (wait_group 1).
// ============================================================================
__global__ void __launch_bounds__(128) gemm_u_kernel(
    const float* __restrict__ Xl, __half* __restrict__ Ul,
    const float* __restrict__ Xt, __half* __restrict__ Ut)
{
    __shared__ __align__(16) float  xa[2][GEMM_ROWS * EDIM];   // 2 x 12800 B
    __shared__ __align__(16) __half uo[2][GEMM_ROWS * 64];     // 2 x 8192 B
    __shared__ __align__(8)  u64t mbar[2];

    const int tid = threadIdx.x, w = tid >> 5, lane = tid & 31;
    const int g = lane >> 2, t = lane & 3;
    const int m0 = w * 16;
    const int tile0 = blockIdx.x * TPC;

    const uint32_t mb0 = smem_u32(&mbar[0]);
    const uint32_t mb1 = smem_u32(&mbar[1]);
    if (tid == 0) { mbar_init(mb0, 1); mbar_init(mb1, 1); }
    __syncthreads();

    if (tid == 0) {
#pragma unroll
        for (int p = 0; p < 2; ++p) {
            const int tt = tile0 + p;
            const float* X = (tt < TL_TILES)
                ? Xl + (size_t)tt * GEMM_ROWS * EDIM
                : Xt + (size_t)(tt - TL_TILES) * GEMM_ROWS * EDIM;
            const uint32_t mb = p ? mb1 : mb0;
            mbar_expect_tx(mb, GEMM_ROWS * EDIM * 4);
            tma_bulk_g2s(smem_u32(&xa[p][0]), X, GEMM_ROWS * EDIM * 4, mb);
        }
    }

    for (int i = 0; i < TPC; ++i) {
        const int cur = i & 1;
        const int tt  = tile0 + i;
        const int mdl = (tt < TL_TILES) ? 0 : 1;
        __half* U = (tt < TL_TILES)
            ? Ul + (size_t)tt * GEMM_ROWS * 64
            : Ut + (size_t)(tt - TL_TILES) * GEMM_ROWS * 64;

        mbar_wait(cur ? mb1 : mb0, (uint32_t)((i >> 1) & 1));

        uint32_t Ah[4][4], Al[4][4];
        const float* xb = &xa[cur][0];
#pragma unroll
        for (int kt = 0; kt < 4; ++kt) {
            const int ko = kt * 16 + t * 2;
#pragma unroll
            for (int half = 0; half < 2; ++half) {
                const int p = ko + half * 8;
                const bool valid = (p < EDIM);
#pragma unroll
                for (int rr = 0; rr < 2; ++rr) {
                    const int row = m0 + g + rr * 8;
                    float2 v = valid ? *(const float2*)(xb + row * EDIM + p)
                                     : make_float2(0.f, 0.f);
                    split_pair(v.x, v.y, Ah[kt][rr + half * 2], Al[kt][rr + half * 2]);
                }
            }
        }
        __syncthreads();

        if (tid == 0 && i + 2 < TPC) {
            const int tn = tile0 + i + 2;
            const float* X = (tn < TL_TILES)
                ? Xl + (size_t)tn * GEMM_ROWS * EDIM
                : Xt + (size_t)(tn - TL_TILES) * GEMM_ROWS * EDIM;
            const uint32_t mb = cur ? mb1 : mb0;
            mbar_expect_tx(mb, GEMM_ROWS * EDIM * 4);
            tma_bulk_g2s(smem_u32(&xa[cur][0]), X, GEMM_ROWS * EDIM * 4, mb);
        }

        const __nv_bfloat16* WH = &g_wh[mdl][0][0];
        const __nv_bfloat16* WL = &g_wl[mdl][0][0];

        if (tid == 0) tma_bulk_store_wait1();
        __syncthreads();

        __half* uw = &uo[cur][0];
#pragma unroll
        for (int nc = 0; nc < 4; ++nc) {
            float c[2][4];
#pragma unroll
            for (int nt = 0; nt < 2; ++nt) { c[nt][0]=c[nt][1]=c[nt][2]=c[nt][3]=0.f; }
#pragma unroll
            for (int kt = 0; kt < 4; ++kt) {
                const int ko = kt * 16 + t * 2;
#pragma unroll
                for (int nt = 0; nt < 2; ++nt) {
                    const int n = nc * 16 + nt * 8 + g;
                    uint32_t bh0 = *(const uint32_t*)(WH + n * 72 + ko);
                    uint32_t bh1 = *(const uint32_t*)(WH + n * 72 + ko + 8);
                    uint32_t bl0 = *(const uint32_t*)(WL + n * 72 + ko);
                    uint32_t bl1 = *(const uint32_t*)(WL + n * 72 + ko + 8);
                    MMA_BF16(c[nt], Ah[kt], bh0, bh1);
                    MMA_BF16(c[nt], Ah[kt], bl0, bl1);
                    MMA_BF16(c[nt], Al[kt], bh0, bh1);
                }
            }
#pragma unroll
            for (int nt = 0; nt < 2; ++nt) {
                const int col = nc * 16 + nt * 8 + t * 2;
                const int row = m0 + g;
                float2 bv = *(const float2*)(&g_bias[mdl][col]);
                *(__half2*)(uw + row * 64 + col) =
                    __float22half2_rn(make_float2(c[nt][0] + bv.x, c[nt][1] + bv.y));
                *(__half2*)(uw + (row + 8) * 64 + col) =
                    __float22half2_rn(make_float2(c[nt][2] + bv.x, c[nt][3] + bv.y));
            }
        }
        __syncthreads();

        if (tid == 0) {
            asm volatile("fence.proxy.async;" ::: "memory");
            tma_bulk_s2g_commit(U, smem_u32(uw), GEMM_ROWS * 64 * 2);
        }
    }
    if (tid == 0) tma_bulk_store_wait0();
}

// ============================================================================
// Tensor-core recurrence: H_t = tanh(U_t + H_{t-1} @ Whh^T), fp16 chain.
// D-frag->A-frag chaining; 16 MMA/step. u prefetch DISTANCE 2 with packed
// half2 buffers (un = t+1, ur = t+2; same reg count as the old distance-1
// float buffers, one extra step of DRAM-latency slack).
// ============================================================================
__global__ void __launch_bounds__(128) rec_tc_kernel()
{
    const int tid = threadIdx.x, w = tid >> 5, lane = tid & 31;
    const int g = lane >> 2, t4 = lane & 3;
    const int blk = blockIdx.x;

    int mdl, dir, T, seq0;
    const __half* U;
    float* Hd;
    if (blk < 2 * REC_TL_CTAS) {
        mdl = 0; T = TTL; U = g_u2; Hd = g_h2;
        dir = blk >> 9;
        seq0 = (blk & 511) * 64;
    } else {
        mdl = 1; T = TTEXT; U = g_u1; Hd = g_hn;
        const int b = blk - 2 * REC_TL_CTAS;
        dir = b >> 3;
        seq0 = (b & 7) * 64;
    }

    uint32_t Bh[2][4][2], Bl[2][4][2];
    {
        const __half* WH = &g_whh_h[mdl][dir][0];
        const __half* WL = &g_whh_l[mdl][dir][0];
#pragma unroll
        for (int kt = 0; kt < 2; ++kt) {
            const int ko = kt * 16 + t4 * 2;
#pragma unroll
            for (int nt = 0; nt < 4; ++nt) {
                const int n = nt * 8 + g;
                Bh[kt][nt][0] = *(const uint32_t*)(WH + n * HDIM + ko);
                Bh[kt][nt][1] = *(const uint32_t*)(WH + n * HDIM + ko + 8);
                Bl[kt][nt][0] = *(const uint32_t*)(WL + n * HDIM + ko);
                Bl[kt][nt][1] = *(const uint32_t*)(WL + n * HDIM + ko + 8);
            }
        }
    }

    const int row = w * 16 + g;
    const int off0 = dir * 32 + t4 * 2;
    const int tt0  = dir ? (T - 1) : 0;
    const int sgnf = dir ? -64 : 64;
    const __half* p = U + ((size_t)(seq0 + row) * T + tt0) * 64 + off0;
    const size_t rstr = (size_t)8 * T * 64;

    // current u as floats in D-frag layout
    float c[4][4];
#pragma unroll
    for (int nt = 0; nt < 4; ++nt) {
        float2 v0 = __half22float2(*(const __half2*)(p + nt * 8));
        float2 v1 = __half22float2(*(const __half2*)(p + rstr + nt * 8));
        c[nt][0] = v0.x; c[nt][1] = v0.y; c[nt][2] = v1.x; c[nt][3] = v1.y;
    }
    // un = packed u_{t+1}  ([nt] row g, [4+nt] row g+8)
    uint32_t un[8];
    if (T > 1) {
        const __half* p1 = p + sgnf;
#pragma unroll
        for (int nt = 0; nt < 4; ++nt) {
            un[nt]     = *(const uint32_t*)(p1 + nt * 8);
            un[4 + nt] = *(const uint32_t*)(p1 + rstr + nt * 8);
        }
    }
    const __half* pf = p + 2 * sgnf;   // source of u_{t+2}

    uint32_t Ah[2][4];
    for (int t = 0; t < T; ++t) {
        // prefetch u_{t+2} (distance-2)
        uint32_t ur[8];
        if (t + 2 < T) {
#pragma unroll
            for (int nt = 0; nt < 4; ++nt) {
                ur[nt]     = *(const uint32_t*)(pf + nt * 8);
                ur[4 + nt] = *(const uint32_t*)(pf + rstr + nt * 8);
            }
        }
        pf += sgnf;

        if (t > 0) {
#pragma unroll
            for (int kt = 0; kt < 2; ++kt) {
#pragma unroll
                for (int nt = 0; nt < 4; ++nt) {
                    MMA_F16(c[nt], Ah[kt], Bh[kt][nt][0], Bh[kt][nt][1]);
                    MMA_F16(c[nt], Ah[kt], Bl[kt][nt][0], Bl[kt][nt][1]);
                }
            }
        }

#pragma unroll
        for (int nt = 0; nt < 4; ++nt) {
#pragma unroll
            for (int j = 0; j < 4; ++j) c[nt][j] = fast_tanh(c[nt][j]);
        }

        if (t + 1 >= T) break;

        // next A (fp16) from D frags
#pragma unroll
        for (int kt = 0; kt < 2; ++kt) {
            const int na = 2 * kt, nb = 2 * kt + 1;
            Ah[kt][0] = pack_h2(c[na][0], c[na][1]);
            Ah[kt][1] = pack_h2(c[na][2], c[na][3]);
            Ah[kt][2] = pack_h2(c[nb][0], c[nb][1]);
            Ah[kt][3] = pack_h2(c[nb][2], c[nb][3]);
        }

        // shift: c <- unpack(un); un <- ur
#pragma unroll
        for (int nt = 0; nt < 4; ++nt) {
            float2 v0 = __half22float2(*(__half2*)&un[nt]);
            float2 v1 = __half22float2(*(__half2*)&un[4 + nt]);
            c[nt][0] = v0.x; c[nt][1] = v0.y; c[nt][2] = v1.x; c[nt][3] = v1.y;
        }
#pragma unroll
        for (int j = 0; j < 8; ++j) un[j] = ur[j];
    }

    float* hb = Hd + (size_t)(seq0 + row) * 64 + off0;
#pragma unroll
    for (int nt = 0; nt < 4; ++nt) {
        *(float2*)(hb + nt * 8)          = make_float2(c[nt][0], c[nt][1]);
        *(float2*)(hb + 8 * 64 + nt * 8) = make_float2(c[nt][2], c[nt][3]);
    }
}

// ============================================================================
// Merged segment stats + head. 128 threads: 2 threads per column scan half
// the rows each (2x load parallelism), combine via smem; then fc1/fc2.
// ============================================================================
__global__ void __launch_bounds__(128) seg_head_kernel(
    const int* __restrict__ elems,
    const float* __restrict__ normal,
    const float* __restrict__ fc1w, const float* __restrict__ fc1b,
    const float* __restrict__ fc2w, const float* __restrict__ fc2b,
    float* __restrict__ out)
{
    const int b    = blockIdx.x;
    const int tid  = threadIdx.x;
    const int wq   = tid >> 5;
    const int lane = tid & 31;
    __shared__ float xr[FC_IN + 3];
    __shared__ float part[4][32];
    __shared__ float sS[64], sMn[64], sMx[64];
    __shared__ int sred[128];

    // prefix sum of elems[0..b)
    int partial = 0;
    for (int i = tid; i < b; i += 128) partial += elems[i];
    sred[tid] = partial;
    __syncthreads();
    for (int s = 64; s; s >>= 1) {
        if (tid < s) sred[tid] += sred[tid + s];
        __syncthreads();
    }
    const int off = sred[0];
    const int cnt = elems[b];

    // column stats: 2 threads per column, each scans half the rows
    {
        const int col  = tid & 63;
        const int hv   = tid >> 6;
        const int r0   = hv ? (cnt >> 1) : 0;
        const int r1   = hv ? cnt : (cnt >> 1);
        float s = 0.f, mn = 3.402823466e38f, mx = -3.402823466e38f;
        const float* base = g_h2 + (size_t)off * 64 + col;
        int r = r0;
        for (; r + 4 <= r1; r += 4) {
            float v0 = base[(size_t)(r + 0) * 64];
            float v1 = base[(size_t)(r + 1) * 64];
            float v2 = base[(size_t)(r + 2) * 64];
            float v3 = base[(size_t)(r + 3) * 64];
            s += (v0 + v1) + (v2 + v3);
            mn = fminf(mn, fminf(fminf(v0, v1), fminf(v2, v3)));
            mx = fmaxf(mx, fmaxf(fmaxf(v0, v1), fmaxf(v2, v3)));
        }
        for (; r < r1; ++r) {
            float v = base[(size_t)r * 64];
            s += v; mn = fminf(mn, v); mx = fmaxf(mx, v);
        }
        if (hv) { sS[col] = s; sMn[col] = mn; sMx[col] = mx; }
        __syncthreads();
        if (!hv) {
            s += sS[col];
            mn = fminf(mn, sMn[col]);
            mx = fmaxf(mx, sMx[col]);
            xr[col]       = g_hn[b * 64 + col];
            xr[113 + col] = s / (float)cnt;
            xr[177 + col] = mn;
            xr[241 + col] = mx;
        }
    }
    for (int i = tid; i < DNORM; i += 128) xr[64 + i] = normal[b * DNORM + i];
    __syncthreads();

    const int k0 = wq * 76;
    const int k1 = (wq == 3) ? FC_IN : k0 + 76;
    const float* wrow = fc1w + lane * FC_IN;
    float a0 = 0.f, a1 = 0.f, a2 = 0.f, a3 = 0.f;
    int k = k0;
    for (; k + 4 <= k1; k += 4) {
        a0 += xr[k]     * wrow[k];
        a1 += xr[k + 1] * wrow[k + 1];
        a2 += xr[k + 2] * wrow[k + 2];
        a3 += xr[k + 3] * wrow[k + 3];
    }
    for (; k < k1; ++k) a0 += xr[k] * wrow[k];
    part[wq][lane] = (a0 + a1) + (a2 + a3);
    __syncthreads();

    if (wq == 0) {
        float acc = fc1b[lane] + part[0][lane] + part[1][lane] + part[2][lane] + part[3][lane];
        float pv = fast_tanh(acc) * fc2w[lane];
#pragma unroll
        for (int o = 16; o; o >>= 1) pv += __shfl_xor_sync(0xffffffffu, pv, o);
        if (lane == 0) out[b] = fast_sigmoid(pv + fc2b[0]);
    }
}

// ============================================================================
// kernel_launch
// ============================================================================
extern "C" void kernel_launch(void* const* d_in, const int* in_sizes, int n_in,
                              void* d_out, int out_size)
{
    const float* normal   = (const float*)d_in[0];
    const float* text     = (const float*)d_in[1];
    const float* timeline = (const float*)d_in[2];

    const int* elems;
    int base;
    if (in_sizes[3] == BATCH) { elems = (const int*)d_in[3]; base = 4; }
    else                      { elems = (const int*)d_in[n_in - 1]; base = 3; }

    const float* r1[8];
    const float* r2[8];
    for (int i = 0; i < 8; ++i) r1[i] = (const float*)d_in[base + i];
    for (int i = 0; i < 8; ++i) r2[i] = (const float*)d_in[base + 8 + i];
    const float* fc1w = (const float*)d_in[base + 16];
    const float* fc1b = (const float*)d_in[base + 17];
    const float* fc2w = (const float*)d_in[base + 18];
    const float* fc2b = (const float*)d_in[base + 19];
    // per dir: wi, wh, bi, bh ; fwd then bwd

    __half* u1; cudaGetSymbolAddress((void**)&u1, g_u1);
    __half* u2; cudaGetSymbolAddress((void**)&u2, g_u2);

    // 1. weight conversion
    setup_w_kernel<<<64, 128>>>(
        r2[0], r2[4], r1[0], r1[4],
        r2[1], r2[5], r1[1], r1[5],
        r2[2], r2[3], r2[6], r2[7],
        r1[2], r1[3], r1[6], r1[7]);

    // 2. persistent tensor-core input GEMM -> fp16 u (768 CTAs)
    gemm_u_kernel<<<GEMM_GRID, 128>>>(timeline, u2, text, u1);

    // 3. tensor-core recurrence (fp16 chain, distance-2 u prefetch)
    rec_tc_kernel<<<REC_GRID, 128>>>();

    // 4. merged segment stats + head
    seg_head_kernel<<<BATCH, 128>>>(elems, normal, fc1w, fc1b, fc2w, fc2b,
                                    (float*)d_out);
}